// round 14
// baseline (speedup 1.0000x reference)
#include <cuda_runtime.h>
#include <cuda_bf16.h>
#include <math.h>
#include <stdint.h>

#define NL 6
#define NB 2
#define NF 16
#define NT 64
#define NS 1024
#define NE 768
#define NH 12
#define DK 64
#define DFF 3072
#define NM (NB*NS)        // 2048 rows
#define NQKV 2304
#define EPS 1e-5f

// ---- scratch (allocation-free rule: __device__ globals) ----
__device__ float g_x[NM*NE];
__device__ float g_tmp[NM*NE];
__device__ float g_tmp2[NM*NE];
__device__ int   g_pad[NB*NS];
__device__ float g_rmax[NB*NH*NS];
__device__ float g_rsum[NB*NH*NS];
// bf16 split planes
__device__ __nv_bfloat16 g_xh[NM*NE],  g_xl[NM*NE];
__device__ __nv_bfloat16 g_qkvh[NM*NQKV], g_qkvl[NM*NQKV];
__device__ __nv_bfloat16 g_ch[NM*NE],  g_cl[NM*NE];            // ctx
__device__ __nv_bfloat16 g_hh[NM*DFF], g_hl[NM*DFF];           // hidden
__device__ __nv_bfloat16 g_ah[(size_t)NB*NH*NS*NS];            // attn hi
__device__ __nv_bfloat16 g_al[(size_t)NB*NH*NS*NS];            // attn lo
// K-major weight planes; QKV concatenated [2304 x 768]
__device__ __nv_bfloat16 g_wqkvh[NL*(size_t)NQKV*NE], g_wqkvl[NL*(size_t)NQKV*NE];
__device__ __nv_bfloat16 g_woh[NL*NE*NE],             g_wol[NL*NE*NE];
__device__ __nv_bfloat16 g_w1h[NL*(size_t)NE*DFF],    g_w1l[NL*(size_t)NE*DFF];
__device__ __nv_bfloat16 g_w2h[NL*(size_t)NE*DFF],    g_w2l[NL*(size_t)NE*DFF];

// ===========================================================================
// PTX helpers (base-sm_103 features only)
// ===========================================================================
__device__ __forceinline__ uint32_t smem_u32(const void* p) {
    uint32_t a;
    asm("{ .reg .u64 t; cvta.to.shared.u64 t, %1; cvt.u32.u64 %0, t; }"
        : "=r"(a) : "l"(p));
    return a;
}
__device__ __forceinline__ void cp16(uint32_t s, const void* g) {
    asm volatile("cp.async.cg.shared.global [%0], [%1], 16;" :: "r"(s), "l"(g));
}
__device__ __forceinline__ void cp_commit() {
    asm volatile("cp.async.commit_group;" ::: "memory");
}
template <int N>
__device__ __forceinline__ void cp_wait() {
    asm volatile("cp.async.wait_group %0;" :: "n"(N) : "memory");
}
__device__ __forceinline__ void ldsm4(uint32_t* r, uint32_t addr) {
    asm volatile("ldmatrix.sync.aligned.m8n8.x4.shared.b16 {%0,%1,%2,%3}, [%4];"
        : "=r"(r[0]), "=r"(r[1]), "=r"(r[2]), "=r"(r[3]) : "r"(addr));
}
__device__ __forceinline__ void ldsm2t(uint32_t* r, uint32_t addr) {
    asm volatile("ldmatrix.sync.aligned.m8n8.x2.trans.shared.b16 {%0,%1}, [%2];"
        : "=r"(r[0]), "=r"(r[1]) : "r"(addr));
}
__device__ __forceinline__ void mma16816(float* c, const uint32_t* a, const uint32_t* b) {
    asm volatile(
        "mma.sync.aligned.m16n8k16.row.col.f32.bf16.bf16.f32 "
        "{%0,%1,%2,%3},{%4,%5,%6,%7},{%8,%9},{%0,%1,%2,%3};"
        : "+f"(c[0]), "+f"(c[1]), "+f"(c[2]), "+f"(c[3])
        : "r"(a[0]), "r"(a[1]), "r"(a[2]), "r"(a[3]), "r"(b[0]), "r"(b[1]));
}
__device__ __forceinline__ void split1(float v, __nv_bfloat16& h, __nv_bfloat16& l) {
    h = __float2bfloat16_rn(v);
    l = __float2bfloat16_rn(v - __bfloat162float(h));
}
__device__ __forceinline__ uint32_t pack_split2(float x0, float x1,
                                                uint32_t& lw) {
    __nv_bfloat16 h0, l0, h1, l1;
    split1(x0, h0, l0); split1(x1, h1, l1);
    lw = (uint32_t)*(uint16_t*)&l0 | ((uint32_t)*(uint16_t*)&l1 << 16);
    return (uint32_t)*(uint16_t*)&h0 | ((uint32_t)*(uint16_t*)&h1 << 16);
}

// ===========================================================================
// Batched weight transpose + split.
// ===========================================================================
__device__ __forceinline__ void tr_body(const float* __restrict__ in,
                                        __nv_bfloat16* __restrict__ oh,
                                        __nv_bfloat16* __restrict__ ol,
                                        int R, int C) {
    __shared__ float tb[32][33];
    int c0 = blockIdx.x * 32, r0 = blockIdx.y * 32;
    int x = threadIdx.x, y = threadIdx.y;   // 32 x 8
#pragma unroll
    for (int i = 0; i < 32; i += 8)
        tb[y + i][x] = in[(size_t)(r0 + y + i) * C + c0 + x];
    __syncthreads();
#pragma unroll
    for (int i = 0; i < 32; i += 8) {
        float v = tb[x][y + i];
        __nv_bfloat16 h, l;
        split1(v, h, l);
        size_t o = (size_t)(c0 + y + i) * R + r0 + x;
        oh[o] = h; ol[o] = l;
    }
}

__global__ void transpose_split_ee(const float* __restrict__ Wq,
                                   const float* __restrict__ Wk,
                                   const float* __restrict__ Wv,
                                   const float* __restrict__ Wo,
                                   __nv_bfloat16* __restrict__ wqkvh,
                                   __nv_bfloat16* __restrict__ wqkvl,
                                   __nv_bfloat16* __restrict__ woh,
                                   __nv_bfloat16* __restrict__ wol) {
    int zc = blockIdx.z, l = zc >> 2, kind = zc & 3;
    size_t oE = (size_t)l * NE * NE;
    size_t oQ = (size_t)l * NQKV * NE;
    const float* in;
    __nv_bfloat16 *oh, *ol;
    if (kind == 0)      { in = Wq + oE; oh = wqkvh + oQ;                    ol = wqkvl + oQ; }
    else if (kind == 1) { in = Wk + oE; oh = wqkvh + oQ + (size_t)NE*NE;    ol = wqkvl + oQ + (size_t)NE*NE; }
    else if (kind == 2) { in = Wv + oE; oh = wqkvh + oQ + (size_t)2*NE*NE;  ol = wqkvl + oQ + (size_t)2*NE*NE; }
    else                { in = Wo + oE; oh = woh + oE;                      ol = wol + oE; }
    tr_body(in, oh, ol, NE, NE);
}

__global__ void transpose_split_w(const float* __restrict__ in0,
                                  __nv_bfloat16* __restrict__ oh0,
                                  __nv_bfloat16* __restrict__ ol0,
                                  int R, int C) {
    size_t off = (size_t)blockIdx.z * NE * DFF;
    tr_body(in0 + off, oh0 + off, ol0 + off, R, C);
}

// ===========================================================================
// bf16x3 mma GEMM (round-8 form)
// ===========================================================================
template <int MODE, bool RELU>
__global__ void __launch_bounds__(128, 2)
bf16_gemm(const __nv_bfloat16* __restrict__ Ah, const __nv_bfloat16* __restrict__ Al,
          const __nv_bfloat16* __restrict__ Bh, const __nv_bfloat16* __restrict__ Bl,
          float* __restrict__ C, float* __restrict__ C2,
          __nv_bfloat16* __restrict__ Ch, __nv_bfloat16* __restrict__ Cl,
          int M, int N, int ldk, int lenK, int ksh) {
    constexpr int BM = 128, BN = 64, WM = 64, WN = 32;
    constexpr int MI = WM / 16;   // 4
    constexpr int NI = WN / 8;    // 4
    constexpr int WGN = BN / WN;  // 2
    constexpr int ROWS = 2 * (BM + BN);      // 384
    constexpr uint32_t SSTR = (uint32_t)ROWS * 80;
    constexpr uint32_t OFF_AH = 0;
    constexpr uint32_t OFF_AL = (uint32_t)BM * 80;
    constexpr uint32_t OFF_BH = (uint32_t)(2 * BM) * 80;
    constexpr uint32_t OFF_BL = (uint32_t)(2 * BM + BN) * 80;

    if (blockIdx.z) { Ah += ksh; Al += ksh; Bh += ksh; Bl += ksh; C = C2; }

    extern __shared__ char smem[];
    uint32_t sbase = smem_u32(smem);
    int tid = threadIdx.x, lane = tid & 31, wid = tid >> 5;
    int wn = wid % WGN, wm = wid / WGN;
    int g = lane >> 2, t = lane & 3;
    int m0 = blockIdx.y * BM, n0 = blockIdx.x * BN;
    const int nk = lenK >> 5;

    auto load_stage = [&](int stage, int k0) {
        uint32_t dst0 = sbase + (uint32_t)stage * SSTR;
#pragma unroll
        for (int idx = tid; idx < ROWS * 4; idx += 128) {
            int r = idx >> 2, c = idx & 3;
            const __nv_bfloat16* src;
            if (r < BM)               src = Ah + (size_t)(m0 + r) * ldk;
            else if (r < 2 * BM)      src = Al + (size_t)(m0 + r - BM) * ldk;
            else if (r < 2 * BM + BN) src = Bh + (size_t)(n0 + r - 2 * BM) * ldk;
            else                      src = Bl + (size_t)(n0 + r - 2 * BM - BN) * ldk;
            cp16(dst0 + (uint32_t)(r * 80 + c * 16), src + k0 + c * 8);
        }
    };

    uint32_t aRel = (uint32_t)((wm * WM + (lane & 15)) * 80 + ((lane >> 4) & 1) * 16);
    uint32_t bRel = (uint32_t)((wn * WN + (lane & 7) + ((lane >> 4) << 3)) * 80
                               + ((lane >> 3) & 1) * 16);

#pragma unroll
    for (int s = 0; s < 3; s++) { load_stage(s, s * 32); cp_commit(); }

    float acc[MI][NI][4];
#pragma unroll
    for (int mi = 0; mi < MI; mi++)
#pragma unroll
        for (int ni = 0; ni < NI; ni++)
#pragma unroll
            for (int j = 0; j < 4; j++) acc[mi][ni][j] = 0.f;

    for (int kc = 0; kc < nk; kc++) {
        int s = kc % 3;
        cp_wait<2>();
        __syncthreads();
        uint32_t stg = sbase + (uint32_t)s * SSTR;

        uint32_t ah[2][MI][4], al[2][MI][4];
        uint32_t bh[2][NI][2], bl[2][NI][2];
#pragma unroll
        for (int u = 0; u < 2; u++) {
            uint32_t koff = (uint32_t)(u * 32);
#pragma unroll
            for (int mi = 0; mi < MI; mi++) {
                ldsm4(ah[u][mi], stg + OFF_AH + aRel + mi * (16 * 80) + koff);
                ldsm4(al[u][mi], stg + OFF_AL + aRel + mi * (16 * 80) + koff);
            }
#pragma unroll
            for (int n2 = 0; n2 < NI / 2; n2++) {
                uint32_t r4[4];
                ldsm4(r4, stg + OFF_BH + bRel + n2 * (16 * 80) + koff);
                bh[u][2*n2][0] = r4[0]; bh[u][2*n2][1] = r4[1];
                bh[u][2*n2+1][0] = r4[2]; bh[u][2*n2+1][1] = r4[3];
                ldsm4(r4, stg + OFF_BL + bRel + n2 * (16 * 80) + koff);
                bl[u][2*n2][0] = r4[0]; bl[u][2*n2][1] = r4[1];
                bl[u][2*n2+1][0] = r4[2]; bl[u][2*n2+1][1] = r4[3];
            }
        }
#pragma unroll
        for (int u = 0; u < 2; u++)
#pragma unroll
            for (int mi = 0; mi < MI; mi++)
#pragma unroll
                for (int ni = 0; ni < NI; ni++) {
                    mma16816(acc[mi][ni], ah[u][mi], bh[u][ni]);
                    mma16816(acc[mi][ni], al[u][mi], bh[u][ni]);
                    mma16816(acc[mi][ni], ah[u][mi], bl[u][ni]);
                }
        __syncthreads();
        if (kc + 3 < nk) load_stage(s, (kc + 3) * 32);
        cp_commit();
    }

#pragma unroll
    for (int mi = 0; mi < MI; mi++) {
        int row0 = m0 + wm * WM + mi * 16 + g;
#pragma unroll
        for (int ni = 0; ni < NI; ni++) {
            int col = n0 + wn * WN + ni * 8 + 2 * t;
            if (MODE == 0) {
                float2 v0, v1;
                v0.x = acc[mi][ni][0]; v0.y = acc[mi][ni][1];
                v1.x = acc[mi][ni][2]; v1.y = acc[mi][ni][3];
                *(float2*)(C + (size_t)row0 * N + col)       = v0;
                *(float2*)(C + (size_t)(row0 + 8) * N + col) = v1;
            } else {
#pragma unroll
                for (int hrow = 0; hrow < 2; hrow++) {
                    int row = row0 + hrow * 8;
                    float x0 = acc[mi][ni][hrow*2+0];
                    float x1 = acc[mi][ni][hrow*2+1];
                    if (RELU) { x0 = fmaxf(x0, 0.f); x1 = fmaxf(x1, 0.f); }
                    uint32_t lw;
                    uint32_t hw = pack_split2(x0, x1, lw);
                    size_t e = ((size_t)row * N + col) >> 1;
                    ((uint32_t*)Ch)[e] = hw;
                    ((uint32_t*)Cl)[e] = lw;
                }
            }
        }
    }
}

// ===========================================================================
// x = x_in + t_pos + s_pos (+ planes) + pad flag (fused), float4 vectorized
// ===========================================================================
__global__ void add_pos_kernel(const float* __restrict__ x,
                               const float* __restrict__ tpos,
                               const float* __restrict__ spos) {
    int i4 = blockIdx.x * blockDim.x + threadIdx.x;
    if (i4 >= NM * NE / 4) return;
    int i = i4 * 4;
    int e = i % NE;
    int s = (i / NE) % NS;
    float4 xv = *(const float4*)(x + i);
    float4 tv = *(const float4*)(tpos + (s / NT) * NE + e);
    float4 sv = *(const float4*)(spos + (s % NT) * NE + e);
    float4 v;
    v.x = xv.x + tv.x + sv.x; v.y = xv.y + tv.y + sv.y;
    v.z = xv.z + tv.z + sv.z; v.w = xv.w + tv.w + sv.w;
    *(float4*)(g_x + i) = v;
    uint32_t lw0, lw1;
    uint32_t hw0 = pack_split2(v.x, v.y, lw0);
    uint32_t hw1 = pack_split2(v.z, v.w, lw1);
    uint2 hv, lv;
    hv.x = hw0; hv.y = hw1; lv.x = lw0; lv.y = lw1;
    *(uint2*)((uint32_t*)g_xh + i4 * 2) = hv;
    *(uint2*)((uint32_t*)g_xl + i4 * 2) = lv;
    if (e == 0) g_pad[i / NE] = (v.x == 0.0f) ? 1 : 0;
}

// ===========================================================================
// scores_stats: per (qt, bh), loop kt<=qt tiles, compute scores in registers
// (identical mma sequence to scores_emit) and accumulate online row max/sum.
// No score writes to DRAM — only 128 (max,sum) pairs per CTA.
// ===========================================================================
#define SST_QH 0
#define SST_QL (128*144)
#define SST_KH (2*128*144)
#define SST_KL (3*128*144)
#define SST_RED (4*128*144)
#define SST_SMEM (SST_RED + 768*4)   // 76,800 B

__global__ void __launch_bounds__(256)
scores_stats(const __nv_bfloat16* __restrict__ qkvh,
             const __nv_bfloat16* __restrict__ qkvl,
             float* __restrict__ rmax, float* __restrict__ rsum) {
    int qt = (int)gridDim.x - 1 - (int)blockIdx.x;   // heavy first
    int bh = blockIdx.y;
    int b = bh / NH, h = bh % NH;

    extern __shared__ char smem[];
    uint32_t sb = smem_u32(smem);
    float* m_run = (float*)(smem + SST_RED);   // [128]
    float* s_run = m_run + 128;                // [128]
    float* tm    = s_run + 128;                // [128][2]
    float* ts    = tm + 256;                   // [128][2]

    int tid = threadIdx.x, lane = tid & 31, wid = tid >> 5;
    int wm = wid >> 1, wn = wid & 1;
    int g = lane >> 2, t = lane & 3;

    if (tid < 128) { m_run[tid] = -1e30f; s_run[tid] = 0.f; }

    // Q tile once
    for (int idx = tid; idx < 128 * 8; idx += 256) {
        int r = idx >> 3, c = idx & 7;
        size_t qrow = (size_t)(b * NS + qt * 128 + r) * NQKV + h * DK + c * 8;
        uint32_t d = (uint32_t)(r * 144 + c * 16);
        cp16(sb + SST_QH + d, qkvh + qrow);
        cp16(sb + SST_QL + d, qkvl + qrow);
    }
    cp_commit();

    uint32_t aRel = (uint32_t)((wm * 32 + (lane & 15)) * 144 + ((lane >> 4) & 1) * 16);
    uint32_t bRel = (uint32_t)((wn * 64 + (lane & 7) + ((lane >> 4) << 3)) * 144
                               + ((lane >> 3) & 1) * 16);
    const float scale = 0.125f;

    for (int kt = 0; kt <= qt; kt++) {
        for (int idx = tid; idx < 128 * 8; idx += 256) {
            int r = idx >> 3, c = idx & 7;
            size_t krow = (size_t)(b * NS + kt * 128 + r) * NQKV + NE + h * DK + c * 8;
            uint32_t d = (uint32_t)(r * 144 + c * 16);
            cp16(sb + SST_KH + d, qkvh + krow);
            cp16(sb + SST_KL + d, qkvl + krow);
        }
        cp_commit();
        cp_wait<0>();
        __syncthreads();

        float acc[2][8][4];
#pragma unroll
        for (int mi = 0; mi < 2; mi++)
#pragma unroll
            for (int ni = 0; ni < 8; ni++)
#pragma unroll
                for (int j = 0; j < 4; j++) acc[mi][ni][j] = 0.f;

#pragma unroll
        for (int kk = 0; kk < 4; kk++) {
            uint32_t koff = (uint32_t)(kk * 32);
            uint32_t ah[2][4], al[2][4];
#pragma unroll
            for (int mi = 0; mi < 2; mi++) {
                ldsm4(ah[mi], sb + SST_QH + aRel + mi * (16 * 144) + koff);
                ldsm4(al[mi], sb + SST_QL + aRel + mi * (16 * 144) + koff);
            }
            uint32_t bh_[8][2], bl_[8][2];
#pragma unroll
            for (int n2 = 0; n2 < 4; n2++) {
                uint32_t r4[4];
                ldsm4(r4, sb + SST_KH + bRel + n2 * (16 * 144) + koff);
                bh_[2*n2][0] = r4[0]; bh_[2*n2][1] = r4[1];
                bh_[2*n2+1][0] = r4[2]; bh_[2*n2+1][1] = r4[3];
                ldsm4(r4, sb + SST_KL + bRel + n2 * (16 * 144) + koff);
                bl_[2*n2][0] = r4[0]; bl_[2*n2][1] = r4[1];
                bl_[2*n2+1][0] = r4[2]; bl_[2*n2+1][1] = r4[3];
            }
#pragma unroll
            for (int mi = 0; mi < 2; mi++)
#pragma unroll
                for (int ni = 0; ni < 8; ni++) {
                    mma16816(acc[mi][ni], ah[mi], bh_[ni]);
                    mma16816(acc[mi][ni], al[mi], bh_[ni]);
                    mma16816(acc[mi][ni], ah[mi], bl_[ni]);
                }
        }

        // phase A: scale+mask in place, per-subrow tile max
#pragma unroll
        for (int mi = 0; mi < 2; mi++)
#pragma unroll
            for (int hrow = 0; hrow < 2; hrow++) {
                int rl = wm * 32 + mi * 16 + g + hrow * 8;
                int qi = qt * 128 + rl;
                float lm = -1e30f;
#pragma unroll
                for (int ni = 0; ni < 8; ni++) {
                    int ki = kt * 128 + wn * 64 + ni * 8 + 2 * t;
                    float v0 = acc[mi][ni][hrow*2+0] * scale;
                    float v1 = acc[mi][ni][hrow*2+1] * scale;
                    if (ki     > qi || g_pad[b * NS + ki])     v0 = -1e9f;
                    if (ki + 1 > qi || g_pad[b * NS + ki + 1]) v1 = -1e9f;
                    acc[mi][ni][hrow*2+0] = v0;
                    acc[mi][ni][hrow*2+1] = v1;
                    lm = fmaxf(lm, fmaxf(v0, v1));
                }
                lm = fmaxf(lm, __shfl_xor_sync(0xffffffffu, lm, 1));
                lm = fmaxf(lm, __shfl_xor_sync(0xffffffffu, lm, 2));
                if (t == 0) tm[rl * 2 + wn] = lm;
            }
        __syncthreads();

        // phase B: per-subrow exp-sum against the combined tile max
#pragma unroll
        for (int mi = 0; mi < 2; mi++)
#pragma unroll
            for (int hrow = 0; hrow < 2; hrow++) {
                int rl = wm * 32 + mi * 16 + g + hrow * 8;
                float M = fmaxf(tm[rl * 2], tm[rl * 2 + 1]);
                float ls = 0.f;
#pragma unroll
                for (int ni = 0; ni < 8; ni++) {
                    ls += __expf(acc[mi][ni][hrow*2+0] - M);
                    ls += __expf(acc[mi][ni][hrow*2+1] - M);
                }
                ls += __shfl_xor_sync(0xffffffffu, ls, 1);
                ls += __shfl_xor_sync(0xffffffffu, ls, 2);
                if (t == 0) ts[rl * 2 + wn] = ls;
            }
        __syncthreads();

        // phase C: online update (one writer per row)
        if (wn == 0 && t == 0) {
#pragma unroll
            for (int mi = 0; mi < 2; mi++)
#pragma unroll
                for (int hrow = 0; hrow < 2; hrow++) {
                    int rl = wm * 32 + mi * 16 + g + hrow * 8;
                    float M = fmaxf(tm[rl * 2], tm[rl * 2 + 1]);
                    float S = ts[rl * 2] + ts[rl * 2 + 1];
                    float mo = m_run[rl], so = s_run[rl];
                    float mn = fmaxf(mo, M);
                    s_run[rl] = so * __expf(mo - mn) + S * __expf(M - mn);
                    m_run[rl] = mn;
                }
        }
        __syncthreads();
    }

    if (tid < 128) {
        size_t o = (size_t)bh * NS + qt * 128 + tid;
        rmax[o] = m_run[tid];
        rsum[o] = s_run[tid];
    }
}

// ===========================================================================
// scores_emit: recompute tile, apply exp/normalize in-register, write FINAL
// fp32 probs + bf16 planes. Upper tiles (kt>qt) write fp32 zeros.
// ===========================================================================
__global__ void __launch_bounds__(256)
scores_emit(const __nv_bfloat16* __restrict__ qkvh,
            const __nv_bfloat16* __restrict__ qkvl,
            const float* __restrict__ rmax, const float* __restrict__ rsum,
            float* __restrict__ attn,
            __nv_bfloat16* __restrict__ ph, __nv_bfloat16* __restrict__ pl) {
    int kt = blockIdx.x, qt = blockIdx.y, bh = blockIdx.z;
    int tid = threadIdx.x;
    if (kt > qt) {
        float* outz = attn + (size_t)bh * NS * NS;
        float4 z; z.x = 0.f; z.y = 0.f; z.z = 0.f; z.w = 0.f;
        for (int idx = tid; idx < 128 * 32; idx += 256) {
            int r = idx >> 5, c4 = idx & 31;
            *(float4*)(outz + (size_t)(qt * 128 + r) * NS + kt * 128 + c4 * 4) = z;
        }
        return;
    }
    int b = bh / NH, h = bh % NH;

    extern __shared__ char smem[];
    uint32_t sb = smem_u32(smem);
    const uint32_t QH = 0, QL = 128*144, KH = 2*128*144, KL = 3*128*144;

    int lane = tid & 31, wid = tid >> 5;
    int wm = wid >> 1, wn = wid & 1;
    int g = lane >> 2, t = lane & 3;

    for (int idx = tid; idx < 128 * 8; idx += 256) {
        int r = idx >> 3, c = idx & 7;
        size_t qrow = (size_t)(b * NS + qt * 128 + r) * NQKV + h * DK + c * 8;
        size_t krow = (size_t)(b * NS + kt * 128 + r) * NQKV + NE + h * DK + c * 8;
        uint32_t d = (uint32_t)(r * 144 + c * 16);
        cp16(sb + QH + d, qkvh + qrow);
        cp16(sb + QL + d, qkvl + qrow);
        cp16(sb + KH + d, qkvh + krow);
        cp16(sb + KL + d, qkvl + krow);
    }
    cp_commit();
    cp_wait<0>();
    __syncthreads();

    uint32_t aRel = (uint32_t)((wm * 32 + (lane & 15)) * 144 + ((lane >> 4) & 1) * 16);
    uint32_t bRel = (uint32_t)((wn * 64 + (lane & 7) + ((lane >> 4) << 3)) * 144
                               + ((lane >> 3) & 1) * 16);

    float acc[2][8][4];
#pragma unroll
    for (int mi = 0; mi < 2; mi++)
#pragma unroll
        for (int ni = 0; ni < 8; ni++)
#pragma unroll
            for (int j = 0; j < 4; j++) acc[mi][ni][j] = 0.f;

#pragma unroll
    for (int kk = 0; kk < 4; kk++) {
        uint32_t koff = (uint32_t)(kk * 32);
        uint32_t ah[2][4], al[2][4];
#pragma unroll
        for (int mi = 0; mi < 2; mi++) {
            ldsm4(ah[mi], sb + QH + aRel + mi * (16 * 144) + koff);
            ldsm4(al[mi], sb + QL + aRel + mi * (16 * 144) + koff);
        }
        uint32_t bh_[8][2], bl_[8][2];
#pragma unroll
        for (int n2 = 0; n2 < 4; n2++) {
            uint32_t r4[4];
            ldsm4(r4, sb + KH + bRel + n2 * (16 * 144) + koff);
            bh_[2*n2][0] = r4[0]; bh_[2*n2][1] = r4[1];
            bh_[2*n2+1][0] = r4[2]; bh_[2*n2+1][1] = r4[3];
            ldsm4(r4, sb + KL + bRel + n2 * (16 * 144) + koff);
            bl_[2*n2][0] = r4[0]; bl_[2*n2][1] = r4[1];
            bl_[2*n2+1][0] = r4[2]; bl_[2*n2+1][1] = r4[3];
        }
#pragma unroll
        for (int mi = 0; mi < 2; mi++)
#pragma unroll
            for (int ni = 0; ni < 8; ni++) {
                mma16816(acc[mi][ni], ah[mi], bh_[ni]);
                mma16816(acc[mi][ni], al[mi], bh_[ni]);
                mma16816(acc[mi][ni], ah[mi], bl_[ni]);
            }
    }

    float* out = attn + (size_t)bh * NS * NS;
    const float scale = 0.125f;
#pragma unroll
    for (int mi = 0; mi < 2; mi++) {
#pragma unroll
        for (int hrow = 0; hrow < 2; hrow++) {
            int qi = qt * 128 + wm * 32 + mi * 16 + g + hrow * 8;
            float M  = rmax[(size_t)bh * NS + qi];
            float Si = 1.0f / rsum[(size_t)bh * NS + qi];
            size_t pbase = (size_t)bh * NS * NS + (size_t)qi * NS;
#pragma unroll
            for (int ni = 0; ni < 8; ni++) {
                int ki = kt * 128 + wn * 64 + ni * 8 + 2 * t;
                float v0 = acc[mi][ni][hrow*2+0] * scale;
                float v1 = acc[mi][ni][hrow*2+1] * scale;
                if (ki     > qi || g_pad[b * NS + ki])     v0 = -1e9f;
                if (ki + 1 > qi || g_pad[b * NS + ki + 1]) v1 = -1e9f;
                float p0 = __expf(v0 - M) * Si;
                float p1 = __expf(v1 - M) * Si;
                float2 v; v.x = p0; v.y = p1;
                *(float2*)(out + (size_t)qi * NS + ki) = v;
                uint32_t lw;
                uint32_t hw = pack_split2(p0, p1, lw);
                ((uint32_t*)ph)[(pbase + ki) >> 1] = hw;
                ((uint32_t*)pl)[(pbase + ki) >> 1] = lw;
            }
        }
    }
}

// ===========================================================================
// ctx_mma: ctx[128q x 64d] = attn_planes @ v_planes (causal kt loop).
// Double-buffered across kt tiles.
// ===========================================================================
#define CTX_SSTR (2*128*272 + 2*128*144)   // 106,496 bytes per stage

__global__ void __launch_bounds__(256)
ctx_mma(const __nv_bfloat16* __restrict__ ph, const __nv_bfloat16* __restrict__ pl,
        const __nv_bfloat16* __restrict__ qkvh, const __nv_bfloat16* __restrict__ qkvl,
        __nv_bfloat16* __restrict__ ch, __nv_bfloat16* __restrict__ cl) {
    int qt = (int)gridDim.x - 1 - (int)blockIdx.x;   // heavy tiles first
    int bh = blockIdx.y;
    int b = bh / NH, h = bh % NH;

    extern __shared__ char smem[];
    uint32_t sb = smem_u32(smem);
    const uint32_t AH = 0, AL = 128*272, VH = 2*128*272, VL = 2*128*272 + 128*144;

    int tid = threadIdx.x, lane = tid & 31, wid = tid >> 5;
    int wm = wid >> 1, wn = wid & 1;
    int g = lane >> 2, t = lane & 3;

    uint32_t aRel = (uint32_t)((wm * 32 + (lane & 15)) * 272 + ((lane >> 4) & 1) * 16);

    auto load_tile = [&](int kt, int st) {
        uint32_t base = sb + (uint32_t)st * CTX_SSTR;
        for (int idx = tid; idx < 128 * 16; idx += 256) {
            int r = idx >> 4, c = idx & 15;
            size_t arow = (size_t)bh * NS * NS + (size_t)(qt * 128 + r) * NS
                        + kt * 128 + c * 8;
            uint32_t d = (uint32_t)(r * 272 + c * 16);
            cp16(base + AH + d, ph + arow);
            cp16(base + AL + d, pl + arow);
        }
        for (int idx = tid; idx < 128 * 8; idx += 256) {
            int r = idx >> 3, c = idx & 7;
            size_t vrow = (size_t)(b * NS + kt * 128 + r) * NQKV + 1536 + h * DK + c * 8;
            uint32_t d = (uint32_t)(r * 144 + c * 16);
            cp16(base + VH + d, qkvh + vrow);
            cp16(base + VL + d, qkvl + vrow);
        }
    };

    float acc[2][4][4];
#pragma unroll
    for (int mi = 0; mi < 2; mi++)
#pragma unroll
        for (int ni = 0; ni < 4; ni++)
#pragma unroll
            for (int j = 0; j < 4; j++) acc[mi][ni][j] = 0.f;

    load_tile(0, 0);
    cp_commit();

    for (int kt = 0; kt <= qt; kt++) {
        int s = kt & 1;
        if (kt < qt) load_tile(kt + 1, s ^ 1);
        cp_commit();
        cp_wait<1>();
        __syncthreads();
        uint32_t base = sb + (uint32_t)s * CTX_SSTR;

#pragma unroll
        for (int kk = 0; kk < 8; kk++) {
            uint32_t koff = (uint32_t)(kk * 32);
            uint32_t ah[2][4], al[2][4];
#pragma unroll
            for (int mi = 0; mi < 2; mi++) {
                ldsm4(ah[mi], base + AH + aRel + mi * (16 * 272) + koff);
                ldsm4(al[mi], base + AL + aRel + mi * (16 * 272) + koff);
            }
            uint32_t vrowRel = (uint32_t)((kk * 16 + (lane & 15)) * 144);
            uint32_t bh_[4][2], bl_[4][2];
#pragma unroll
            for (int ni = 0; ni < 4; ni++) {
                uint32_t coff = (uint32_t)((wn * 32 + ni * 8) * 2);
                ldsm2t(bh_[ni], base + VH + vrowRel + coff);
                ldsm2t(bl_[ni], base + VL + vrowRel + coff);
            }
#pragma unroll
            for (int mi = 0; mi < 2; mi++)
#pragma unroll
                for (int ni = 0; ni < 4; ni++) {
                    mma16816(acc[mi][ni], ah[mi], bh_[ni]);
                    mma16816(acc[mi][ni], al[mi], bh_[ni]);
                    mma16816(acc[mi][ni], ah[mi], bl_[ni]);
                }
        }
        __syncthreads();
    }

#pragma unroll
    for (int mi = 0; mi < 2; mi++) {
#pragma unroll
        for (int ni = 0; ni < 4; ni++) {
            int dcol = h * DK + wn * 32 + ni * 8 + 2 * t;
#pragma unroll
            for (int hrow = 0; hrow < 2; hrow++) {
                int q = qt * 128 + wm * 32 + mi * 16 + g + hrow * 8;
                uint32_t lw;
                uint32_t hw = pack_split2(acc[mi][ni][hrow*2], acc[mi][ni][hrow*2+1], lw);
                size_t e = ((size_t)(b * NS + q) * NE + dcol) >> 1;
                ((uint32_t*)ch)[e] = hw;
                ((uint32_t*)cl)[e] = lw;
            }
        }
    }
}

// ===========================================================================
// x = LayerNorm(y1 [+ y2] + x) * g + b  (192 threads, float4; writes planes;
// optional extra fp32 destination xout)
// ===========================================================================
__global__ void __launch_bounds__(192)
ln_kernel(const float* __restrict__ y1,
          const float* __restrict__ y2,
          float* __restrict__ xio,
          float* __restrict__ xout,
          const float* __restrict__ gamma,
          const float* __restrict__ beta) {
    int row = blockIdx.x;
    __shared__ float red[8];
    int tid = threadIdx.x;
    size_t rbase = (size_t)row * NE;

    int i = tid * 4;
    float4 a = *(const float4*)(y1 + rbase + i);
    float4 c = *(const float4*)(xio + rbase + i);
    float4 v;
    v.x = a.x + c.x; v.y = a.y + c.y; v.z = a.z + c.z; v.w = a.w + c.w;
    if (y2) {
        float4 d = *(const float4*)(y2 + rbase + i);
        v.x += d.x; v.y += d.y; v.z += d.z; v.w += d.w;
    }
    float s = (v.x + v.y) + (v.z + v.w);
#pragma unroll
    for (int o = 16; o; o >>= 1) s += __shfl_xor_sync(0xffffffffu, s, o);
    if ((tid & 31) == 0) red[tid >> 5] = s;
    __syncthreads();
    if (tid < 32) {
        float r = (tid < 6) ? red[tid] : 0.f;
#pragma unroll
        for (int o = 4; o; o >>= 1) r += __shfl_xor_sync(0xffffffffu, r, o);
        if (tid == 0) red[0] = r;
    }
    __syncthreads();
    float mean = red[0] * (1.0f / NE);
    __syncthreads();

    float dx = v.x - mean, dy = v.y - mean, dz = v.z - mean, dw = v.w - mean;
    float vs = (dx * dx + dy * dy) + (dz * dz + dw * dw);
#pragma unroll
    for (int o = 16; o; o >>= 1) vs += __shfl_xor_sync(0xffffffffu, vs, o);
    if ((tid & 31) == 0) red[tid >> 5] = vs;
    __syncthreads();
    if (tid < 32) {
        float r = (tid < 6) ? red[tid] : 0.f;
#pragma unroll
        for (int o = 4; o; o >>= 1) r += __shfl_xor_sync(0xffffffffu, r, o);
        if (tid == 0) red[0] = r;
    }
    __syncthreads();
    float rstd = rsqrtf(red[0] * (1.0f / NE) + EPS);

    float4 gm = *(const float4*)(gamma + i);
    float4 bt = *(const float4*)(beta + i);
    float4 o;
    o.x = dx * rstd * gm.x + bt.x;
    o.y = dy * rstd * gm.y + bt.y;
    o.z = dz * rstd * gm.z + bt.z;
    o.w = dw * rstd * gm.w + bt.w;
    *(float4*)(xio + rbase + i) = o;
    if (xout) *(float4*)(xout + rbase + i) = o;
    uint32_t lw0, lw1;
    uint32_t hw0 = pack_split2(o.x, o.y, lw0);
    uint32_t hw1 = pack_split2(o.z, o.w, lw1);
    uint2 hv, lv;
    hv.x = hw0; hv.y = hw1; lv.x = lw0; lv.y = lw1;
    *(uint2*)((uint32_t*)g_xh + ((rbase + i) >> 1)) = hv;
    *(uint2*)((uint32_t*)g_xl + ((rbase + i) >> 1)) = lv;
}

// ===========================================================================
extern "C" void kernel_launch(void* const* d_in, const int* in_sizes, int n_in,
                              void* d_out, int out_size) {
    const float* x    = (const float*)d_in[0];
    const float* tpos = (const float*)d_in[1];
    const float* spos = (const float*)d_in[2];
    const float* Wq   = (const float*)d_in[3];
    const float* Wk   = (const float*)d_in[4];
    const float* Wv   = (const float*)d_in[5];
    const float* Wo   = (const float*)d_in[6];
    const float* ln1g = (const float*)d_in[7];
    const float* ln1b = (const float*)d_in[8];
    const float* W1   = (const float*)d_in[9];
    const float* W2   = (const float*)d_in[10];
    const float* ln2g = (const float*)d_in[11];
    const float* ln2b = (const float*)d_in[12];

    float* out      = (float*)d_out;
    float* attn_out = out + (size_t)NM * NE;

    float *px, *ptmp, *ptmp2, *prmax, *prsum;
    __nv_bfloat16 *pxh, *pxl, *pqkvh, *pqkvl, *pch, *pcl, *phh, *phl, *pah, *pal;
    __nv_bfloat16 *pwqkvh, *pwqkvl, *pwoh, *pwol, *pw1h, *pw1l, *pw2h, *pw2l;
    cudaGetSymbolAddress((void**)&px,    g_x);
    cudaGetSymbolAddress((void**)&ptmp,  g_tmp);
    cudaGetSymbolAddress((void**)&ptmp2, g_tmp2);
    cudaGetSymbolAddress((void**)&prmax, g_rmax);
    cudaGetSymbolAddress((void**)&prsum, g_rsum);
    cudaGetSymbolAddress((void**)&pxh,   g_xh);
    cudaGetSymbolAddress((void**)&pxl,   g_xl);
    cudaGetSymbolAddress((void**)&pqkvh, g_qkvh);
    cudaGetSymbolAddress((void**)&pqkvl, g_qkvl);
    cudaGetSymbolAddress((void**)&pch,   g_ch);
    cudaGetSymbolAddress((void**)&pcl,   g_cl);
    cudaGetSymbolAddress((void**)&phh,   g_hh);
    cudaGetSymbolAddress((void**)&phl,   g_hl);
    cudaGetSymbolAddress((void**)&pah,   g_ah);
    cudaGetSymbolAddress((void**)&pal,   g_al);
    cudaGetSymbolAddress((void**)&pwqkvh, g_wqkvh);
    cudaGetSymbolAddress((void**)&pwqkvl, g_wqkvl);
    cudaGetSymbolAddress((void**)&pwoh,  g_woh);
    cudaGetSymbolAddress((void**)&pwol,  g_wol);
    cudaGetSymbolAddress((void**)&pw1h,  g_w1h);
    cudaGetSymbolAddress((void**)&pw1l,  g_w1l);
    cudaGetSymbolAddress((void**)&pw2h,  g_w2h);
    cudaGetSymbolAddress((void**)&pw2l,  g_w2l);

    const int SM_P  = 2 * (128 + 64) * 80 * 3;       //  92,160
    const int SM_SC = 4 * 128 * 144;                 //  73,728
    const int SM_ST = SST_SMEM;                      //  76,800
    const int SM_CX = 2 * CTX_SSTR;                  // 212,992

    cudaFuncSetAttribute((const void*)bf16_gemm<0,false>,
        cudaFuncAttributeMaxDynamicSharedMemorySize, SM_P);
    cudaFuncSetAttribute((const void*)bf16_gemm<1,false>,
        cudaFuncAttributeMaxDynamicSharedMemorySize, SM_P);
    cudaFuncSetAttribute((const void*)bf16_gemm<1,true>,
        cudaFuncAttributeMaxDynamicSharedMemorySize, SM_P);
    cudaFuncSetAttribute((const void*)scores_stats,
        cudaFuncAttributeMaxDynamicSharedMemorySize, SM_ST);
    cudaFuncSetAttribute((const void*)scores_emit,
        cudaFuncAttributeMaxDynamicSharedMemorySize, SM_SC);
    cudaFuncSetAttribute((const void*)ctx_mma,
        cudaFuncAttributeMaxDynamicSharedMemorySize, SM_CX);

    add_pos_kernel<<<(NM * NE / 4 + 255) / 256, 256>>>(x, tpos, spos);

    {
        dim3 blk(32, 8);
        transpose_split_ee<<<dim3(NE/32, NE/32, NL*4), blk>>>(
            Wq, Wk, Wv, Wo, pwqkvh, pwqkvl, pwoh, pwol);
        transpose_split_w<<<dim3(DFF/32, NE/32, NL), blk>>>(W1, pw1h, pw1l, NE, DFF);
        transpose_split_w<<<dim3(NE/32, DFF/32, NL), blk>>>(W2, pw2h, pw2l, DFF, NE);
    }

    dim3 gQKV(NQKV / 64, NM / 128, 1);         // (36, 16)
    dim3 gWo(NE / 64, NM / 128, 2);            // (12, 16, 2) split-K merged
    dim3 gFF1(DFF / 64, NM / 128, 1);          // (48, 16)
    dim3 gFF2(NE / 64, NM / 128, 2);           // (12, 16, 2) split-K merged
    dim3 gStat(NS / 128, NB * NH);             // (8, 24)
    dim3 gEmit(NS / 128, NS / 128, NB * NH);   // (8, 8, 24)
    dim3 gCtx(NS / 128, NB * NH);              // (8, 24)

    for (int l = 0; l < NL; l++) {
        size_t oE = (size_t)l * NE * NE, oF = (size_t)l * NE * DFF;
        size_t oQ = (size_t)l * NQKV * NE;
        float* attn_l = attn_out + (size_t)l * NB * NH * NS * NS;
        float* xout2 = (l == NL - 1) ? out : nullptr;

        bf16_gemm<1,false><<<gQKV, 128, SM_P>>>(
            pxh, pxl, pwqkvh + oQ, pwqkvl + oQ,
            nullptr, nullptr, pqkvh, pqkvl, NM, NQKV, NE, NE, 0);

        scores_stats<<<gStat, 256, SM_ST>>>(pqkvh, pqkvl, prmax, prsum);
        scores_emit<<<gEmit, 256, SM_SC>>>(pqkvh, pqkvl, prmax, prsum,
                                           attn_l, pah, pal);
        ctx_mma<<<gCtx, 256, SM_CX>>>(pah, pal, pqkvh, pqkvl, pch, pcl);

        bf16_gemm<0,false><<<gWo, 128, SM_P>>>(
            pch, pcl, pwoh + oE, pwol + oE, ptmp, ptmp2, nullptr, nullptr,
            NM, NE, NE, 384, 384);
        ln_kernel<<<NM, 192>>>(ptmp, ptmp2, px, nullptr,
                               ln1g + (size_t)l * NE, ln1b + (size_t)l * NE);

        bf16_gemm<1,true><<<gFF1, 128, SM_P>>>(
            pxh, pxl, pw1h + oF, pw1l + oF, nullptr, nullptr, phh, phl,
            NM, DFF, NE, NE, 0);

        bf16_gemm<0,false><<<gFF2, 128, SM_P>>>(
            phh, phl, pw2h + oF, pw2l + oF, ptmp, ptmp2, nullptr, nullptr,
            NM, NE, DFF, 1536, 1536);
        ln_kernel<<<NM, 192>>>(ptmp, ptmp2, px, xout2,
                               ln2g + (size_t)l * NE, ln2b + (size_t)l * NE);
    }
}

// round 15
// speedup vs baseline: 1.0951x; 1.0951x over previous
#include <cuda_runtime.h>
#include <cuda_bf16.h>
#include <math.h>
#include <stdint.h>

#define NL 6
#define NB 2
#define NF 16
#define NT 64
#define NS 1024
#define NE 768
#define NH 12
#define DK 64
#define DFF 3072
#define NM (NB*NS)        // 2048 rows
#define NQKV 2304
#define EPS 1e-5f

// ---- scratch (allocation-free rule: __device__ globals) ----
__device__ float g_x[NM*NE];
__device__ float g_tmp[NM*NE];
__device__ float g_tmp2[NM*NE];
__device__ int   g_pad[NB*NS];
// bf16 split planes
__device__ __nv_bfloat16 g_xh[NM*NE],  g_xl[NM*NE];
__device__ __nv_bfloat16 g_qkvh[NM*NQKV], g_qkvl[NM*NQKV];
__device__ __nv_bfloat16 g_ch[NM*NE],  g_cl[NM*NE];            // ctx
__device__ __nv_bfloat16 g_hh[NM*DFF], g_hl[NM*DFF];           // hidden
__device__ __nv_bfloat16 g_ah[(size_t)NB*NH*NS*NS];            // attn hi
__device__ __nv_bfloat16 g_al[(size_t)NB*NH*NS*NS];            // attn lo
// K-major weight planes; QKV concatenated [2304 x 768]
__device__ __nv_bfloat16 g_wqkvh[NL*(size_t)NQKV*NE], g_wqkvl[NL*(size_t)NQKV*NE];
__device__ __nv_bfloat16 g_woh[NL*NE*NE],             g_wol[NL*NE*NE];
__device__ __nv_bfloat16 g_w1h[NL*(size_t)NE*DFF],    g_w1l[NL*(size_t)NE*DFF];
__device__ __nv_bfloat16 g_w2h[NL*(size_t)NE*DFF],    g_w2l[NL*(size_t)NE*DFF];

// ===========================================================================
// PTX helpers (base-sm_103 features only)
// ===========================================================================
__device__ __forceinline__ uint32_t smem_u32(const void* p) {
    uint32_t a;
    asm("{ .reg .u64 t; cvta.to.shared.u64 t, %1; cvt.u32.u64 %0, t; }"
        : "=r"(a) : "l"(p));
    return a;
}
__device__ __forceinline__ void cp16(uint32_t s, const void* g) {
    asm volatile("cp.async.cg.shared.global [%0], [%1], 16;" :: "r"(s), "l"(g));
}
__device__ __forceinline__ void cp_commit() {
    asm volatile("cp.async.commit_group;" ::: "memory");
}
template <int N>
__device__ __forceinline__ void cp_wait() {
    asm volatile("cp.async.wait_group %0;" :: "n"(N) : "memory");
}
__device__ __forceinline__ void ldsm4(uint32_t* r, uint32_t addr) {
    asm volatile("ldmatrix.sync.aligned.m8n8.x4.shared.b16 {%0,%1,%2,%3}, [%4];"
        : "=r"(r[0]), "=r"(r[1]), "=r"(r[2]), "=r"(r[3]) : "r"(addr));
}
__device__ __forceinline__ void ldsm2t(uint32_t* r, uint32_t addr) {
    asm volatile("ldmatrix.sync.aligned.m8n8.x2.trans.shared.b16 {%0,%1}, [%2];"
        : "=r"(r[0]), "=r"(r[1]) : "r"(addr));
}
__device__ __forceinline__ void mma16816(float* c, const uint32_t* a, const uint32_t* b) {
    asm volatile(
        "mma.sync.aligned.m16n8k16.row.col.f32.bf16.bf16.f32 "
        "{%0,%1,%2,%3},{%4,%5,%6,%7},{%8,%9},{%0,%1,%2,%3};"
        : "+f"(c[0]), "+f"(c[1]), "+f"(c[2]), "+f"(c[3])
        : "r"(a[0]), "r"(a[1]), "r"(a[2]), "r"(a[3]), "r"(b[0]), "r"(b[1]));
}
__device__ __forceinline__ void split1(float v, __nv_bfloat16& h, __nv_bfloat16& l) {
    h = __float2bfloat16_rn(v);
    l = __float2bfloat16_rn(v - __bfloat162float(h));
}
__device__ __forceinline__ uint32_t pack_split2(float x0, float x1,
                                                uint32_t& lw) {
    __nv_bfloat16 h0, l0, h1, l1;
    split1(x0, h0, l0); split1(x1, h1, l1);
    lw = (uint32_t)*(uint16_t*)&l0 | ((uint32_t)*(uint16_t*)&l1 << 16);
    return (uint32_t)*(uint16_t*)&h0 | ((uint32_t)*(uint16_t*)&h1 << 16);
}

// ===========================================================================
// Batched weight transpose + split, uint32-packed stores (row pairs).
// tile: 32 input rows (r) x 32 input cols (c); out[c][r] planes.
// ===========================================================================
__device__ __forceinline__ void tr_body(const float* __restrict__ in,
                                        __nv_bfloat16* __restrict__ oh,
                                        __nv_bfloat16* __restrict__ ol,
                                        int R, int C) {
    __shared__ float tb[32][34];
    int c0 = blockIdx.x * 32, r0 = blockIdx.y * 32;
    int x = threadIdx.x, y = threadIdx.y;   // 32 x 8
#pragma unroll
    for (int i = 0; i < 32; i += 8)
        tb[y + i][x] = in[(size_t)(r0 + y + i) * C + c0 + x];
    __syncthreads();
    int tid = y * 32 + x;                   // 0..255
#pragma unroll
    for (int k = tid; k < 32 * 16; k += 256) {
        int cc = k >> 4, pr = k & 15;       // output row c0+cc, r-pair pr
        float v0 = tb[2 * pr][cc];
        float v1 = tb[2 * pr + 1][cc];
        uint32_t lw;
        uint32_t hw = pack_split2(v0, v1, lw);
        size_t base = ((size_t)(c0 + cc) * R + r0) >> 1;   // uint32 units
        ((uint32_t*)oh)[base + pr] = hw;
        ((uint32_t*)ol)[base + pr] = lw;
    }
}

__global__ void transpose_split_ee(const float* __restrict__ Wq,
                                   const float* __restrict__ Wk,
                                   const float* __restrict__ Wv,
                                   const float* __restrict__ Wo,
                                   __nv_bfloat16* __restrict__ wqkvh,
                                   __nv_bfloat16* __restrict__ wqkvl,
                                   __nv_bfloat16* __restrict__ woh,
                                   __nv_bfloat16* __restrict__ wol) {
    int zc = blockIdx.z, l = zc >> 2, kind = zc & 3;
    size_t oE = (size_t)l * NE * NE;
    size_t oQ = (size_t)l * NQKV * NE;
    const float* in;
    __nv_bfloat16 *oh, *ol;
    if (kind == 0)      { in = Wq + oE; oh = wqkvh + oQ;                    ol = wqkvl + oQ; }
    else if (kind == 1) { in = Wk + oE; oh = wqkvh + oQ + (size_t)NE*NE;    ol = wqkvl + oQ + (size_t)NE*NE; }
    else if (kind == 2) { in = Wv + oE; oh = wqkvh + oQ + (size_t)2*NE*NE;  ol = wqkvl + oQ + (size_t)2*NE*NE; }
    else                { in = Wo + oE; oh = woh + oE;                      ol = wol + oE; }
    tr_body(in, oh, ol, NE, NE);
}

__global__ void transpose_split_w(const float* __restrict__ in0,
                                  __nv_bfloat16* __restrict__ oh0,
                                  __nv_bfloat16* __restrict__ ol0,
                                  int R, int C) {
    size_t off = (size_t)blockIdx.z * NE * DFF;
    tr_body(in0 + off, oh0 + off, ol0 + off, R, C);
}

// ===========================================================================
// bf16x3 mma GEMM (round-8 form, unchanged)
// ===========================================================================
template <int MODE, bool RELU>
__global__ void __launch_bounds__(128, 2)
bf16_gemm(const __nv_bfloat16* __restrict__ Ah, const __nv_bfloat16* __restrict__ Al,
          const __nv_bfloat16* __restrict__ Bh, const __nv_bfloat16* __restrict__ Bl,
          float* __restrict__ C, float* __restrict__ C2,
          __nv_bfloat16* __restrict__ Ch, __nv_bfloat16* __restrict__ Cl,
          int M, int N, int ldk, int lenK, int ksh) {
    constexpr int BM = 128, BN = 64, WM = 64, WN = 32;
    constexpr int MI = WM / 16;   // 4
    constexpr int NI = WN / 8;    // 4
    constexpr int WGN = BN / WN;  // 2
    constexpr int ROWS = 2 * (BM + BN);      // 384
    constexpr uint32_t SSTR = (uint32_t)ROWS * 80;
    constexpr uint32_t OFF_AH = 0;
    constexpr uint32_t OFF_AL = (uint32_t)BM * 80;
    constexpr uint32_t OFF_BH = (uint32_t)(2 * BM) * 80;
    constexpr uint32_t OFF_BL = (uint32_t)(2 * BM + BN) * 80;

    if (blockIdx.z) { Ah += ksh; Al += ksh; Bh += ksh; Bl += ksh; C = C2; }

    extern __shared__ char smem[];
    uint32_t sbase = smem_u32(smem);
    int tid = threadIdx.x, lane = tid & 31, wid = tid >> 5;
    int wn = wid % WGN, wm = wid / WGN;
    int g = lane >> 2, t = lane & 3;
    int m0 = blockIdx.y * BM, n0 = blockIdx.x * BN;
    const int nk = lenK >> 5;

    auto load_stage = [&](int stage, int k0) {
        uint32_t dst0 = sbase + (uint32_t)stage * SSTR;
#pragma unroll
        for (int idx = tid; idx < ROWS * 4; idx += 128) {
            int r = idx >> 2, c = idx & 3;
            const __nv_bfloat16* src;
            if (r < BM)               src = Ah + (size_t)(m0 + r) * ldk;
            else if (r < 2 * BM)      src = Al + (size_t)(m0 + r - BM) * ldk;
            else if (r < 2 * BM + BN) src = Bh + (size_t)(n0 + r - 2 * BM) * ldk;
            else                      src = Bl + (size_t)(n0 + r - 2 * BM - BN) * ldk;
            cp16(dst0 + (uint32_t)(r * 80 + c * 16), src + k0 + c * 8);
        }
    };

    uint32_t aRel = (uint32_t)((wm * WM + (lane & 15)) * 80 + ((lane >> 4) & 1) * 16);
    uint32_t bRel = (uint32_t)((wn * WN + (lane & 7) + ((lane >> 4) << 3)) * 80
                               + ((lane >> 3) & 1) * 16);

#pragma unroll
    for (int s = 0; s < 3; s++) { load_stage(s, s * 32); cp_commit(); }

    float acc[MI][NI][4];
#pragma unroll
    for (int mi = 0; mi < MI; mi++)
#pragma unroll
        for (int ni = 0; ni < NI; ni++)
#pragma unroll
            for (int j = 0; j < 4; j++) acc[mi][ni][j] = 0.f;

    for (int kc = 0; kc < nk; kc++) {
        int s = kc % 3;
        cp_wait<2>();
        __syncthreads();
        uint32_t stg = sbase + (uint32_t)s * SSTR;

        uint32_t ah[2][MI][4], al[2][MI][4];
        uint32_t bh[2][NI][2], bl[2][NI][2];
#pragma unroll
        for (int u = 0; u < 2; u++) {
            uint32_t koff = (uint32_t)(u * 32);
#pragma unroll
            for (int mi = 0; mi < MI; mi++) {
                ldsm4(ah[u][mi], stg + OFF_AH + aRel + mi * (16 * 80) + koff);
                ldsm4(al[u][mi], stg + OFF_AL + aRel + mi * (16 * 80) + koff);
            }
#pragma unroll
            for (int n2 = 0; n2 < NI / 2; n2++) {
                uint32_t r4[4];
                ldsm4(r4, stg + OFF_BH + bRel + n2 * (16 * 80) + koff);
                bh[u][2*n2][0] = r4[0]; bh[u][2*n2][1] = r4[1];
                bh[u][2*n2+1][0] = r4[2]; bh[u][2*n2+1][1] = r4[3];
                ldsm4(r4, stg + OFF_BL + bRel + n2 * (16 * 80) + koff);
                bl[u][2*n2][0] = r4[0]; bl[u][2*n2][1] = r4[1];
                bl[u][2*n2+1][0] = r4[2]; bl[u][2*n2+1][1] = r4[3];
            }
        }
#pragma unroll
        for (int u = 0; u < 2; u++)
#pragma unroll
            for (int mi = 0; mi < MI; mi++)
#pragma unroll
                for (int ni = 0; ni < NI; ni++) {
                    mma16816(acc[mi][ni], ah[u][mi], bh[u][ni]);
                    mma16816(acc[mi][ni], al[u][mi], bh[u][ni]);
                    mma16816(acc[mi][ni], ah[u][mi], bl[u][ni]);
                }
        __syncthreads();
        if (kc + 3 < nk) load_stage(s, (kc + 3) * 32);
        cp_commit();
    }

#pragma unroll
    for (int mi = 0; mi < MI; mi++) {
        int row0 = m0 + wm * WM + mi * 16 + g;
#pragma unroll
        for (int ni = 0; ni < NI; ni++) {
            int col = n0 + wn * WN + ni * 8 + 2 * t;
            if (MODE == 0) {
                float2 v0, v1;
                v0.x = acc[mi][ni][0]; v0.y = acc[mi][ni][1];
                v1.x = acc[mi][ni][2]; v1.y = acc[mi][ni][3];
                *(float2*)(C + (size_t)row0 * N + col)       = v0;
                *(float2*)(C + (size_t)(row0 + 8) * N + col) = v1;
            } else {
#pragma unroll
                for (int hrow = 0; hrow < 2; hrow++) {
                    int row = row0 + hrow * 8;
                    float x0 = acc[mi][ni][hrow*2+0];
                    float x1 = acc[mi][ni][hrow*2+1];
                    if (RELU) { x0 = fmaxf(x0, 0.f); x1 = fmaxf(x1, 0.f); }
                    uint32_t lw;
                    uint32_t hw = pack_split2(x0, x1, lw);
                    size_t e = ((size_t)row * N + col) >> 1;
                    ((uint32_t*)Ch)[e] = hw;
                    ((uint32_t*)Cl)[e] = lw;
                }
            }
        }
    }
}

// ===========================================================================
// x = x_in + t_pos + s_pos  (+ bf16 split planes), float4 vectorized
// ===========================================================================
__global__ void add_pos_kernel(const float* __restrict__ x,
                               const float* __restrict__ tpos,
                               const float* __restrict__ spos) {
    int i4 = blockIdx.x * blockDim.x + threadIdx.x;
    if (i4 >= NM * NE / 4) return;
    int i = i4 * 4;
    int e = i % NE;
    int s = (i / NE) % NS;
    float4 xv = *(const float4*)(x + i);
    float4 tv = *(const float4*)(tpos + (s / NT) * NE + e);
    float4 sv = *(const float4*)(spos + (s % NT) * NE + e);
    float4 v;
    v.x = xv.x + tv.x + sv.x; v.y = xv.y + tv.y + sv.y;
    v.z = xv.z + tv.z + sv.z; v.w = xv.w + tv.w + sv.w;
    *(float4*)(g_x + i) = v;
    uint32_t lw0, lw1;
    uint32_t hw0 = pack_split2(v.x, v.y, lw0);
    uint32_t hw1 = pack_split2(v.z, v.w, lw1);
    uint2 hv, lv;
    hv.x = hw0; hv.y = hw1; lv.x = lw0; lv.y = lw1;
    *(uint2*)((uint32_t*)g_xh + i4 * 2) = hv;
    *(uint2*)((uint32_t*)g_xl + i4 * 2) = lv;
}

__global__ void pad_kernel() {
    int i = blockIdx.x * blockDim.x + threadIdx.x;
    if (i < NB * NS) g_pad[i] = (g_x[(size_t)i * NE] == 0.0f) ? 1 : 0;
}

// ===========================================================================
// scores_mma: 128x128 tile of q.k^T * scale, causal+pad masked -> fp32 attn.
// ===========================================================================
__global__ void __launch_bounds__(256)
scores_mma(const __nv_bfloat16* __restrict__ qkvh,
           const __nv_bfloat16* __restrict__ qkvl,
           float* __restrict__ attn) {
    int kt = blockIdx.x, qt = blockIdx.y, bh = blockIdx.z;
    if (kt > qt) return;
    int b = bh / NH, h = bh % NH;

    extern __shared__ char smem[];
    uint32_t sb = smem_u32(smem);
    const uint32_t QH = 0, QL = 128*144, KH = 2*128*144, KL = 3*128*144;

    int tid = threadIdx.x, lane = tid & 31, wid = tid >> 5;
    int wm = wid >> 1, wn = wid & 1;
    int g = lane >> 2, t = lane & 3;

    for (int idx = tid; idx < 128 * 8; idx += 256) {
        int r = idx >> 3, c = idx & 7;
        size_t qrow = (size_t)(b * NS + qt * 128 + r) * NQKV + h * DK + c * 8;
        size_t krow = (size_t)(b * NS + kt * 128 + r) * NQKV + NE + h * DK + c * 8;
        uint32_t d = (uint32_t)(r * 144 + c * 16);
        cp16(sb + QH + d, qkvh + qrow);
        cp16(sb + QL + d, qkvl + qrow);
        cp16(sb + KH + d, qkvh + krow);
        cp16(sb + KL + d, qkvl + krow);
    }
    cp_commit();
    cp_wait<0>();
    __syncthreads();

    uint32_t aRel = (uint32_t)((wm * 32 + (lane & 15)) * 144 + ((lane >> 4) & 1) * 16);
    uint32_t bRel = (uint32_t)((wn * 64 + (lane & 7) + ((lane >> 4) << 3)) * 144
                               + ((lane >> 3) & 1) * 16);

    float acc[2][8][4];
#pragma unroll
    for (int mi = 0; mi < 2; mi++)
#pragma unroll
        for (int ni = 0; ni < 8; ni++)
#pragma unroll
            for (int j = 0; j < 4; j++) acc[mi][ni][j] = 0.f;

#pragma unroll
    for (int kk = 0; kk < 4; kk++) {
        uint32_t koff = (uint32_t)(kk * 32);
        uint32_t ah[2][4], al[2][4];
#pragma unroll
        for (int mi = 0; mi < 2; mi++) {
            ldsm4(ah[mi], sb + QH + aRel + mi * (16 * 144) + koff);
            ldsm4(al[mi], sb + QL + aRel + mi * (16 * 144) + koff);
        }
        uint32_t bh_[8][2], bl_[8][2];
#pragma unroll
        for (int n2 = 0; n2 < 4; n2++) {
            uint32_t r4[4];
            ldsm4(r4, sb + KH + bRel + n2 * (16 * 144) + koff);
            bh_[2*n2][0] = r4[0]; bh_[2*n2][1] = r4[1];
            bh_[2*n2+1][0] = r4[2]; bh_[2*n2+1][1] = r4[3];
            ldsm4(r4, sb + KL + bRel + n2 * (16 * 144) + koff);
            bl_[2*n2][0] = r4[0]; bl_[2*n2][1] = r4[1];
            bl_[2*n2+1][0] = r4[2]; bl_[2*n2+1][1] = r4[3];
        }
#pragma unroll
        for (int mi = 0; mi < 2; mi++)
#pragma unroll
            for (int ni = 0; ni < 8; ni++) {
                mma16816(acc[mi][ni], ah[mi], bh_[ni]);
                mma16816(acc[mi][ni], al[mi], bh_[ni]);
                mma16816(acc[mi][ni], ah[mi], bl_[ni]);
            }
    }

    float* out = attn + (size_t)bh * NS * NS;
    const float scale = 0.125f;
#pragma unroll
    for (int mi = 0; mi < 2; mi++) {
#pragma unroll
        for (int hrow = 0; hrow < 2; hrow++) {
            int qi = qt * 128 + wm * 32 + mi * 16 + g + hrow * 8;
#pragma unroll
            for (int ni = 0; ni < 8; ni++) {
                int ki = kt * 128 + wn * 64 + ni * 8 + 2 * t;
                float v0 = acc[mi][ni][hrow*2+0] * scale;
                float v1 = acc[mi][ni][hrow*2+1] * scale;
                if (ki     > qi || g_pad[b * NS + ki])     v0 = -1e9f;
                if (ki + 1 > qi || g_pad[b * NS + ki + 1]) v1 = -1e9f;
                float2 v; v.x = v0; v.y = v1;
                *(float2*)(out + (size_t)qi * NS + ki) = v;
            }
        }
    }
}

// ===========================================================================
// Warp-per-row softmax (round-8 form): writes fp32 probs (incl causal zeros)
// and bf16 split planes (zero-padded to the 128-tile boundary).
// ===========================================================================
__global__ void __launch_bounds__(256)
softmax_kernel(float* __restrict__ attn,
               __nv_bfloat16* __restrict__ ph,
               __nv_bfloat16* __restrict__ pl) {
    int wid = threadIdx.x >> 5, lane = threadIdx.x & 31;
    int q  = blockIdx.x * 8 + wid;
    int bh = blockIdx.y;
    size_t pbase = (size_t)bh * NS * NS + (size_t)q * NS;
    float* row = attn + pbase;
    int n = q + 1;
    int npad = (n + 127) & ~127;

    float4 v[8];
    float m = -1e30f;
#pragma unroll
    for (int j = 0; j < 8; j++) {
        int e0 = (lane + 32 * j) * 4;
        if (e0 < n) {
            float4 tv = *(const float4*)(row + e0);
            v[j].x = tv.x;
            v[j].y = (e0 + 1 < n) ? tv.y : -1e30f;
            v[j].z = (e0 + 2 < n) ? tv.z : -1e30f;
            v[j].w = (e0 + 3 < n) ? tv.w : -1e30f;
        } else {
            v[j].x = -1e30f; v[j].y = -1e30f; v[j].z = -1e30f; v[j].w = -1e30f;
        }
        m = fmaxf(m, fmaxf(fmaxf(v[j].x, v[j].y), fmaxf(v[j].z, v[j].w)));
    }
#pragma unroll
    for (int o = 16; o; o >>= 1) m = fmaxf(m, __shfl_xor_sync(0xffffffffu, m, o));

    float s = 0.f;
#pragma unroll
    for (int j = 0; j < 8; j++) {
        v[j].x = __expf(v[j].x - m);
        v[j].y = __expf(v[j].y - m);
        v[j].z = __expf(v[j].z - m);
        v[j].w = __expf(v[j].w - m);
        s += (v[j].x + v[j].y) + (v[j].z + v[j].w);
    }
#pragma unroll
    for (int o = 16; o; o >>= 1) s += __shfl_xor_sync(0xffffffffu, s, o);
    float inv = 1.0f / s;

#pragma unroll
    for (int j = 0; j < 8; j++) {
        int e0 = (lane + 32 * j) * 4;
        float4 p;
        p.x = v[j].x * inv; p.y = v[j].y * inv;
        p.z = v[j].z * inv; p.w = v[j].w * inv;
        *(float4*)(row + e0) = p;             // probs for i<n, exact 0 beyond
        if (e0 < npad) {
            uint32_t lw0, lw1;
            uint32_t hw0 = pack_split2(p.x, p.y, lw0);
            uint32_t hw1 = pack_split2(p.z, p.w, lw1);
            uint2 hv, lv;
            hv.x = hw0; hv.y = hw1; lv.x = lw0; lv.y = lw1;
            *(uint2*)((uint32_t*)ph + ((pbase + e0) >> 1)) = hv;
            *(uint2*)((uint32_t*)pl + ((pbase + e0) >> 1)) = lv;
        }
    }
}

// ===========================================================================
// ctx_mma: ctx[128q x 64d] = attn_planes @ v_planes (causal kt loop).
// Double-buffered across kt tiles.
// ===========================================================================
#define CTX_SSTR (2*128*272 + 2*128*144)   // 106,496 bytes per stage

__global__ void __launch_bounds__(256)
ctx_mma(const __nv_bfloat16* __restrict__ ph, const __nv_bfloat16* __restrict__ pl,
        const __nv_bfloat16* __restrict__ qkvh, const __nv_bfloat16* __restrict__ qkvl,
        __nv_bfloat16* __restrict__ ch, __nv_bfloat16* __restrict__ cl) {
    int qt = (int)gridDim.x - 1 - (int)blockIdx.x;   // heavy tiles first
    int bh = blockIdx.y;
    int b = bh / NH, h = bh % NH;

    extern __shared__ char smem[];
    uint32_t sb = smem_u32(smem);
    const uint32_t AH = 0, AL = 128*272, VH = 2*128*272, VL = 2*128*272 + 128*144;

    int tid = threadIdx.x, lane = tid & 31, wid = tid >> 5;
    int wm = wid >> 1, wn = wid & 1;
    int g = lane >> 2, t = lane & 3;

    uint32_t aRel = (uint32_t)((wm * 32 + (lane & 15)) * 272 + ((lane >> 4) & 1) * 16);

    auto load_tile = [&](int kt, int st) {
        uint32_t base = sb + (uint32_t)st * CTX_SSTR;
        for (int idx = tid; idx < 128 * 16; idx += 256) {
            int r = idx >> 4, c = idx & 15;
            size_t arow = (size_t)bh * NS * NS + (size_t)(qt * 128 + r) * NS
                        + kt * 128 + c * 8;
            uint32_t d = (uint32_t)(r * 272 + c * 16);
            cp16(base + AH + d, ph + arow);
            cp16(base + AL + d, pl + arow);
        }
        for (int idx = tid; idx < 128 * 8; idx += 256) {
            int r = idx >> 3, c = idx & 7;
            size_t vrow = (size_t)(b * NS + kt * 128 + r) * NQKV + 1536 + h * DK + c * 8;
            uint32_t d = (uint32_t)(r * 144 + c * 16);
            cp16(base + VH + d, qkvh + vrow);
            cp16(base + VL + d, qkvl + vrow);
        }
    };

    float acc[2][4][4];
#pragma unroll
    for (int mi = 0; mi < 2; mi++)
#pragma unroll
        for (int ni = 0; ni < 4; ni++)
#pragma unroll
            for (int j = 0; j < 4; j++) acc[mi][ni][j] = 0.f;

    load_tile(0, 0);
    cp_commit();

    for (int kt = 0; kt <= qt; kt++) {
        int s = kt & 1;
        if (kt < qt) load_tile(kt + 1, s ^ 1);
        cp_commit();
        cp_wait<1>();
        __syncthreads();
        uint32_t base = sb + (uint32_t)s * CTX_SSTR;

#pragma unroll
        for (int kk = 0; kk < 8; kk++) {
            uint32_t koff = (uint32_t)(kk * 32);
            uint32_t ah[2][4], al[2][4];
#pragma unroll
            for (int mi = 0; mi < 2; mi++) {
                ldsm4(ah[mi], base + AH + aRel + mi * (16 * 272) + koff);
                ldsm4(al[mi], base + AL + aRel + mi * (16 * 272) + koff);
            }
            uint32_t vrowRel = (uint32_t)((kk * 16 + (lane & 15)) * 144);
            uint32_t bh_[4][2], bl_[4][2];
#pragma unroll
            for (int ni = 0; ni < 4; ni++) {
                uint32_t coff = (uint32_t)((wn * 32 + ni * 8) * 2);
                ldsm2t(bh_[ni], base + VH + vrowRel + coff);
                ldsm2t(bl_[ni], base + VL + vrowRel + coff);
            }
#pragma unroll
            for (int mi = 0; mi < 2; mi++)
#pragma unroll
                for (int ni = 0; ni < 4; ni++) {
                    mma16816(acc[mi][ni], ah[mi], bh_[ni]);
                    mma16816(acc[mi][ni], al[mi], bh_[ni]);
                    mma16816(acc[mi][ni], ah[mi], bl_[ni]);
                }
        }
        __syncthreads();
    }

#pragma unroll
    for (int mi = 0; mi < 2; mi++) {
#pragma unroll
        for (int ni = 0; ni < 4; ni++) {
            int dcol = h * DK + wn * 32 + ni * 8 + 2 * t;
#pragma unroll
            for (int hrow = 0; hrow < 2; hrow++) {
                int q = qt * 128 + wm * 32 + mi * 16 + g + hrow * 8;
                uint32_t lw;
                uint32_t hw = pack_split2(acc[mi][ni][hrow*2], acc[mi][ni][hrow*2+1], lw);
                size_t e = ((size_t)(b * NS + q) * NE + dcol) >> 1;
                ((uint32_t*)ch)[e] = hw;
                ((uint32_t*)cl)[e] = lw;
            }
        }
    }
}

// ===========================================================================
// x = LayerNorm(y1 [+ y2] + x) * g + b  (round-8 form: 256 thr, smem buf;
// optional extra fp32 destination xout)
// ===========================================================================
__global__ void ln_kernel(const float* __restrict__ y1,
                          const float* __restrict__ y2,
                          float* __restrict__ xio,
                          float* __restrict__ xout,
                          const float* __restrict__ gamma,
                          const float* __restrict__ beta) {
    int row = blockIdx.x;
    __shared__ float buf[NE];
    __shared__ float red[8];
    int tid = threadIdx.x;
    size_t rbase = (size_t)row * NE;

    float s = 0.f;
    if (tid < 192) {
        int i = tid * 4;
        float4 a = *(const float4*)(y1 + rbase + i);
        float4 c = *(const float4*)(xio + rbase + i);
        float4 v;
        v.x = a.x + c.x; v.y = a.y + c.y; v.z = a.z + c.z; v.w = a.w + c.w;
        if (y2) {
            float4 d = *(const float4*)(y2 + rbase + i);
            v.x += d.x; v.y += d.y; v.z += d.z; v.w += d.w;
        }
        *(float4*)(buf + i) = v;
        s = (v.x + v.y) + (v.z + v.w);
    }
#pragma unroll
    for (int o = 16; o; o >>= 1) s += __shfl_xor_sync(0xffffffffu, s, o);
    if ((tid & 31) == 0) red[tid >> 5] = s;
    __syncthreads();
    if (tid < 32) {
        float r = (tid < 8) ? red[tid] : 0.f;
#pragma unroll
        for (int o = 4; o; o >>= 1) r += __shfl_xor_sync(0xffffffffu, r, o);
        if (tid == 0) red[0] = r;
    }
    __syncthreads();
    float mean = red[0] * (1.0f / NE);
    __syncthreads();

    float vs = 0.f;
    if (tid < 192) {
        float4 v = *(const float4*)(buf + tid * 4);
        float dx = v.x - mean, dy = v.y - mean, dz = v.z - mean, dw = v.w - mean;
        vs = (dx * dx + dy * dy) + (dz * dz + dw * dw);
    }
#pragma unroll
    for (int o = 16; o; o >>= 1) vs += __shfl_xor_sync(0xffffffffu, vs, o);
    if ((tid & 31) == 0) red[tid >> 5] = vs;
    __syncthreads();
    if (tid < 32) {
        float r = (tid < 8) ? red[tid] : 0.f;
#pragma unroll
        for (int o = 4; o; o >>= 1) r += __shfl_xor_sync(0xffffffffu, r, o);
        if (tid == 0) red[0] = r;
    }
    __syncthreads();
    float rstd = rsqrtf(red[0] * (1.0f / NE) + EPS);

    if (tid < 192) {
        int i = tid * 4;
        float4 v = *(const float4*)(buf + i);
        float4 gm = *(const float4*)(gamma + i);
        float4 bt = *(const float4*)(beta + i);
        float4 o;
        o.x = (v.x - mean) * rstd * gm.x + bt.x;
        o.y = (v.y - mean) * rstd * gm.y + bt.y;
        o.z = (v.z - mean) * rstd * gm.z + bt.z;
        o.w = (v.w - mean) * rstd * gm.w + bt.w;
        *(float4*)(xio + rbase + i) = o;
        if (xout) *(float4*)(xout + rbase + i) = o;
        uint32_t lw0, lw1;
        uint32_t hw0 = pack_split2(o.x, o.y, lw0);
        uint32_t hw1 = pack_split2(o.z, o.w, lw1);
        uint2 hv, lv;
        hv.x = hw0; hv.y = hw1; lv.x = lw0; lv.y = lw1;
        *(uint2*)((uint32_t*)g_xh + ((rbase + i) >> 1)) = hv;
        *(uint2*)((uint32_t*)g_xl + ((rbase + i) >> 1)) = lv;
    }
}

// ===========================================================================
extern "C" void kernel_launch(void* const* d_in, const int* in_sizes, int n_in,
                              void* d_out, int out_size) {
    const float* x    = (const float*)d_in[0];
    const float* tpos = (const float*)d_in[1];
    const float* spos = (const float*)d_in[2];
    const float* Wq   = (const float*)d_in[3];
    const float* Wk   = (const float*)d_in[4];
    const float* Wv   = (const float*)d_in[5];
    const float* Wo   = (const float*)d_in[6];
    const float* ln1g = (const float*)d_in[7];
    const float* ln1b = (const float*)d_in[8];
    const float* W1   = (const float*)d_in[9];
    const float* W2   = (const float*)d_in[10];
    const float* ln2g = (const float*)d_in[11];
    const float* ln2b = (const float*)d_in[12];

    float* out      = (float*)d_out;
    float* attn_out = out + (size_t)NM * NE;

    float *px, *ptmp, *ptmp2;
    __nv_bfloat16 *pxh, *pxl, *pqkvh, *pqkvl, *pch, *pcl, *phh, *phl, *pah, *pal;
    __nv_bfloat16 *pwqkvh, *pwqkvl, *pwoh, *pwol, *pw1h, *pw1l, *pw2h, *pw2l;
    cudaGetSymbolAddress((void**)&px,    g_x);
    cudaGetSymbolAddress((void**)&ptmp,  g_tmp);
    cudaGetSymbolAddress((void**)&ptmp2, g_tmp2);
    cudaGetSymbolAddress((void**)&pxh,   g_xh);
    cudaGetSymbolAddress((void**)&pxl,   g_xl);
    cudaGetSymbolAddress((void**)&pqkvh, g_qkvh);
    cudaGetSymbolAddress((void**)&pqkvl, g_qkvl);
    cudaGetSymbolAddress((void**)&pch,   g_ch);
    cudaGetSymbolAddress((void**)&pcl,   g_cl);
    cudaGetSymbolAddress((void**)&phh,   g_hh);
    cudaGetSymbolAddress((void**)&phl,   g_hl);
    cudaGetSymbolAddress((void**)&pah,   g_ah);
    cudaGetSymbolAddress((void**)&pal,   g_al);
    cudaGetSymbolAddress((void**)&pwqkvh, g_wqkvh);
    cudaGetSymbolAddress((void**)&pwqkvl, g_wqkvl);
    cudaGetSymbolAddress((void**)&pwoh,  g_woh);
    cudaGetSymbolAddress((void**)&pwol,  g_wol);
    cudaGetSymbolAddress((void**)&pw1h,  g_w1h);
    cudaGetSymbolAddress((void**)&pw1l,  g_w1l);
    cudaGetSymbolAddress((void**)&pw2h,  g_w2h);
    cudaGetSymbolAddress((void**)&pw2l,  g_w2l);

    const int SM_P  = 2 * (128 + 64) * 80 * 3;       //  92,160
    const int SM_SC = 4 * 128 * 144;                 //  73,728
    const int SM_CX = 2 * CTX_SSTR;                  // 212,992

    cudaFuncSetAttribute((const void*)bf16_gemm<0,false>,
        cudaFuncAttributeMaxDynamicSharedMemorySize, SM_P);
    cudaFuncSetAttribute((const void*)bf16_gemm<1,false>,
        cudaFuncAttributeMaxDynamicSharedMemorySize, SM_P);
    cudaFuncSetAttribute((const void*)bf16_gemm<1,true>,
        cudaFuncAttributeMaxDynamicSharedMemorySize, SM_P);
    cudaFuncSetAttribute((const void*)scores_mma,
        cudaFuncAttributeMaxDynamicSharedMemorySize, SM_SC);
    cudaFuncSetAttribute((const void*)ctx_mma,
        cudaFuncAttributeMaxDynamicSharedMemorySize, SM_CX);

    add_pos_kernel<<<(NM * NE / 4 + 255) / 256, 256>>>(x, tpos, spos);
    pad_kernel<<<(NB * NS + 255) / 256, 256>>>();

    {
        dim3 blk(32, 8);
        transpose_split_ee<<<dim3(NE/32, NE/32, NL*4), blk>>>(
            Wq, Wk, Wv, Wo, pwqkvh, pwqkvl, pwoh, pwol);
        transpose_split_w<<<dim3(DFF/32, NE/32, NL), blk>>>(W1, pw1h, pw1l, NE, DFF);
        transpose_split_w<<<dim3(NE/32, DFF/32, NL), blk>>>(W2, pw2h, pw2l, DFF, NE);
    }

    dim3 gQKV(NQKV / 64, NM / 128, 1);         // (36, 16)
    dim3 gWo(NE / 64, NM / 128, 2);            // (12, 16, 2) split-K merged
    dim3 gFF1(DFF / 64, NM / 128, 1);          // (48, 16)
    dim3 gFF2(NE / 64, NM / 128, 2);           // (12, 16, 2) split-K merged
    dim3 gScores(NS / 128, NS / 128, NB * NH); // (8, 8, 24)
    dim3 gSoft(NS / 8, NB * NH);               // (128, 24) warp-per-row
    dim3 gCtx(NS / 128, NB * NH);              // (8, 24)

    for (int l = 0; l < NL; l++) {
        size_t oE = (size_t)l * NE * NE, oF = (size_t)l * NE * DFF;
        size_t oQ = (size_t)l * NQKV * NE;
        float* attn_l = attn_out + (size_t)l * NB * NH * NS * NS;
        float* xout2 = (l == NL - 1) ? out : nullptr;

        bf16_gemm<1,false><<<gQKV, 128, SM_P>>>(
            pxh, pxl, pwqkvh + oQ, pwqkvl + oQ,
            nullptr, nullptr, pqkvh, pqkvl, NM, NQKV, NE, NE, 0);

        scores_mma<<<gScores, 256, SM_SC>>>(pqkvh, pqkvl, attn_l);
        softmax_kernel<<<gSoft, 256>>>(attn_l, pah, pal);
        ctx_mma<<<gCtx, 256, SM_CX>>>(pah, pal, pqkvh, pqkvl, pch, pcl);

        bf16_gemm<0,false><<<gWo, 128, SM_P>>>(
            pch, pcl, pwoh + oE, pwol + oE, ptmp, ptmp2, nullptr, nullptr,
            NM, NE, NE, 384, 384);
        ln_kernel<<<NM, 256>>>(ptmp, ptmp2, px, nullptr,
                               ln1g + (size_t)l * NE, ln1b + (size_t)l * NE);

        bf16_gemm<1,true><<<gFF1, 128, SM_P>>>(
            pxh, pxl, pw1h + oF, pw1l + oF, nullptr, nullptr, phh, phl,
            NM, DFF, NE, NE, 0);

        bf16_gemm<0,false><<<gFF2, 128, SM_P>>>(
            phh, phl, pw2h + oF, pw2l + oF, ptmp, ptmp2, nullptr, nullptr,
            NM, NE, DFF, 1536, 1536);
        ln_kernel<<<NM, 256>>>(ptmp, ptmp2, px, xout2,
                               ln2g + (size_t)l * NE, ln2b + (size_t)l * NE);
    }
}

// round 17
// speedup vs baseline: 1.0954x; 1.0003x over previous
#include <cuda_runtime.h>
#include <cuda_bf16.h>
#include <math.h>
#include <stdint.h>

#define NL 6
#define NB 2
#define NF 16
#define NT 64
#define NS 1024
#define NE 768
#define NH 12
#define DK 64
#define DFF 3072
#define NM (NB*NS)        // 2048 rows
#define NQKV 2304
#define EPS 1e-5f

// ---- scratch (allocation-free rule: __device__ globals) ----
__device__ float g_x[NM*NE];
__device__ float g_tmp[NM*NE];
__device__ float g_tmp2[NM*NE];
__device__ int   g_pad[NB*NS];
// bf16 split planes
__device__ __nv_bfloat16 g_xh[NM*NE],  g_xl[NM*NE];
__device__ __nv_bfloat16 g_qkvh[NM*NQKV], g_qkvl[NM*NQKV];
__device__ __nv_bfloat16 g_ch[NM*NE],  g_cl[NM*NE];            // ctx
__device__ __nv_bfloat16 g_hh[NM*DFF], g_hl[NM*DFF];           // hidden
__device__ __nv_bfloat16 g_ah[(size_t)NB*NH*NS*NS];            // attn hi
__device__ __nv_bfloat16 g_al[(size_t)NB*NH*NS*NS];            // attn lo
// K-major weight planes; QKV concatenated [2304 x 768]
__device__ __nv_bfloat16 g_wqkvh[NL*(size_t)NQKV*NE], g_wqkvl[NL*(size_t)NQKV*NE];
__device__ __nv_bfloat16 g_woh[NL*NE*NE],             g_wol[NL*NE*NE];
__device__ __nv_bfloat16 g_w1h[NL*(size_t)NE*DFF],    g_w1l[NL*(size_t)NE*DFF];
__device__ __nv_bfloat16 g_w2h[NL*(size_t)NE*DFF],    g_w2l[NL*(size_t)NE*DFF];

// ===========================================================================
// PTX helpers (base-sm_103 features only)
// ===========================================================================
__device__ __forceinline__ uint32_t smem_u32(const void* p) {
    uint32_t a;
    asm("{ .reg .u64 t; cvta.to.shared.u64 t, %1; cvt.u32.u64 %0, t; }"
        : "=r"(a) : "l"(p));
    return a;
}
__device__ __forceinline__ void cp16(uint32_t s, const void* g) {
    asm volatile("cp.async.cg.shared.global [%0], [%1], 16;" :: "r"(s), "l"(g));
}
__device__ __forceinline__ void cp_commit() {
    asm volatile("cp.async.commit_group;" ::: "memory");
}
template <int N>
__device__ __forceinline__ void cp_wait() {
    asm volatile("cp.async.wait_group %0;" :: "n"(N) : "memory");
}
__device__ __forceinline__ void ldsm4(uint32_t* r, uint32_t addr) {
    asm volatile("ldmatrix.sync.aligned.m8n8.x4.shared.b16 {%0,%1,%2,%3}, [%4];"
        : "=r"(r[0]), "=r"(r[1]), "=r"(r[2]), "=r"(r[3]) : "r"(addr));
}
__device__ __forceinline__ void ldsm2t(uint32_t* r, uint32_t addr) {
    asm volatile("ldmatrix.sync.aligned.m8n8.x2.trans.shared.b16 {%0,%1}, [%2];"
        : "=r"(r[0]), "=r"(r[1]) : "r"(addr));
}
__device__ __forceinline__ void mma16816(float* c, const uint32_t* a, const uint32_t* b) {
    asm volatile(
        "mma.sync.aligned.m16n8k16.row.col.f32.bf16.bf16.f32 "
        "{%0,%1,%2,%3},{%4,%5,%6,%7},{%8,%9},{%0,%1,%2,%3};"
        : "+f"(c[0]), "+f"(c[1]), "+f"(c[2]), "+f"(c[3])
        : "r"(a[0]), "r"(a[1]), "r"(a[2]), "r"(a[3]), "r"(b[0]), "r"(b[1]));
}
__device__ __forceinline__ void split1(float v, __nv_bfloat16& h, __nv_bfloat16& l) {
    h = __float2bfloat16_rn(v);
    l = __float2bfloat16_rn(v - __bfloat162float(h));
}
__device__ __forceinline__ uint32_t pack_split2(float x0, float x1,
                                                uint32_t& lw) {
    __nv_bfloat16 h0, l0, h1, l1;
    split1(x0, h0, l0); split1(x1, h1, l1);
    lw = (uint32_t)*(uint16_t*)&l0 | ((uint32_t)*(uint16_t*)&l1 << 16);
    return (uint32_t)*(uint16_t*)&h0 | ((uint32_t)*(uint16_t*)&h1 << 16);
}

// ===========================================================================
// Batched weight transpose + split, uint32-packed stores (row pairs).
// ===========================================================================
__device__ __forceinline__ void tr_body(const float* __restrict__ in,
                                        __nv_bfloat16* __restrict__ oh,
                                        __nv_bfloat16* __restrict__ ol,
                                        int R, int C) {
    __shared__ float tb[32][34];
    int c0 = blockIdx.x * 32, r0 = blockIdx.y * 32;
    int x = threadIdx.x, y = threadIdx.y;   // 32 x 8
#pragma unroll
    for (int i = 0; i < 32; i += 8)
        tb[y + i][x] = in[(size_t)(r0 + y + i) * C + c0 + x];
    __syncthreads();
    int tid = y * 32 + x;                   // 0..255
#pragma unroll
    for (int k = tid; k < 32 * 16; k += 256) {
        int cc = k >> 4, pr = k & 15;       // output row c0+cc, r-pair pr
        float v0 = tb[2 * pr][cc];
        float v1 = tb[2 * pr + 1][cc];
        uint32_t lw;
        uint32_t hw = pack_split2(v0, v1, lw);
        size_t base = ((size_t)(c0 + cc) * R + r0) >> 1;   // uint32 units
        ((uint32_t*)oh)[base + pr] = hw;
        ((uint32_t*)ol)[base + pr] = lw;
    }
}

__global__ void transpose_split_ee(const float* __restrict__ Wq,
                                   const float* __restrict__ Wk,
                                   const float* __restrict__ Wv,
                                   const float* __restrict__ Wo,
                                   __nv_bfloat16* __restrict__ wqkvh,
                                   __nv_bfloat16* __restrict__ wqkvl,
                                   __nv_bfloat16* __restrict__ woh,
                                   __nv_bfloat16* __restrict__ wol) {
    int zc = blockIdx.z, l = zc >> 2, kind = zc & 3;
    size_t oE = (size_t)l * NE * NE;
    size_t oQ = (size_t)l * NQKV * NE;
    const float* in;
    __nv_bfloat16 *oh, *ol;
    if (kind == 0)      { in = Wq + oE; oh = wqkvh + oQ;                    ol = wqkvl + oQ; }
    else if (kind == 1) { in = Wk + oE; oh = wqkvh + oQ + (size_t)NE*NE;    ol = wqkvl + oQ + (size_t)NE*NE; }
    else if (kind == 2) { in = Wv + oE; oh = wqkvh + oQ + (size_t)2*NE*NE;  ol = wqkvl + oQ + (size_t)2*NE*NE; }
    else                { in = Wo + oE; oh = woh + oE;                      ol = wol + oE; }
    tr_body(in, oh, ol, NE, NE);
}

__global__ void transpose_split_w(const float* __restrict__ in0,
                                  __nv_bfloat16* __restrict__ oh0,
                                  __nv_bfloat16* __restrict__ ol0,
                                  int R, int C) {
    size_t off = (size_t)blockIdx.z * NE * DFF;
    tr_body(in0 + off, oh0 + off, ol0 + off, R, C);
}

// ===========================================================================
// bf16x3 mma GEMM (round-8 form, unchanged)
// ===========================================================================
template <int MODE, bool RELU>
__global__ void __launch_bounds__(128, 2)
bf16_gemm(const __nv_bfloat16* __restrict__ Ah, const __nv_bfloat16* __restrict__ Al,
          const __nv_bfloat16* __restrict__ Bh, const __nv_bfloat16* __restrict__ Bl,
          float* __restrict__ C, float* __restrict__ C2,
          __nv_bfloat16* __restrict__ Ch, __nv_bfloat16* __restrict__ Cl,
          int M, int N, int ldk, int lenK, int ksh) {
    constexpr int BM = 128, BN = 64, WM = 64, WN = 32;
    constexpr int MI = WM / 16;   // 4
    constexpr int NI = WN / 8;    // 4
    constexpr int WGN = BN / WN;  // 2
    constexpr int ROWS = 2 * (BM + BN);      // 384
    constexpr uint32_t SSTR = (uint32_t)ROWS * 80;
    constexpr uint32_t OFF_AH = 0;
    constexpr uint32_t OFF_AL = (uint32_t)BM * 80;
    constexpr uint32_t OFF_BH = (uint32_t)(2 * BM) * 80;
    constexpr uint32_t OFF_BL = (uint32_t)(2 * BM + BN) * 80;

    if (blockIdx.z) { Ah += ksh; Al += ksh; Bh += ksh; Bl += ksh; C = C2; }

    extern __shared__ char smem[];
    uint32_t sbase = smem_u32(smem);
    int tid = threadIdx.x, lane = tid & 31, wid = tid >> 5;
    int wn = wid % WGN, wm = wid / WGN;
    int g = lane >> 2, t = lane & 3;
    int m0 = blockIdx.y * BM, n0 = blockIdx.x * BN;
    const int nk = lenK >> 5;

    auto load_stage = [&](int stage, int k0) {
        uint32_t dst0 = sbase + (uint32_t)stage * SSTR;
#pragma unroll
        for (int idx = tid; idx < ROWS * 4; idx += 128) {
            int r = idx >> 2, c = idx & 3;
            const __nv_bfloat16* src;
            if (r < BM)               src = Ah + (size_t)(m0 + r) * ldk;
            else if (r < 2 * BM)      src = Al + (size_t)(m0 + r - BM) * ldk;
            else if (r < 2 * BM + BN) src = Bh + (size_t)(n0 + r - 2 * BM) * ldk;
            else                      src = Bl + (size_t)(n0 + r - 2 * BM - BN) * ldk;
            cp16(dst0 + (uint32_t)(r * 80 + c * 16), src + k0 + c * 8);
        }
    };

    uint32_t aRel = (uint32_t)((wm * WM + (lane & 15)) * 80 + ((lane >> 4) & 1) * 16);
    uint32_t bRel = (uint32_t)((wn * WN + (lane & 7) + ((lane >> 4) << 3)) * 80
                               + ((lane >> 3) & 1) * 16);

#pragma unroll
    for (int s = 0; s < 3; s++) { load_stage(s, s * 32); cp_commit(); }

    float acc[MI][NI][4];
#pragma unroll
    for (int mi = 0; mi < MI; mi++)
#pragma unroll
        for (int ni = 0; ni < NI; ni++)
#pragma unroll
            for (int j = 0; j < 4; j++) acc[mi][ni][j] = 0.f;

    for (int kc = 0; kc < nk; kc++) {
        int s = kc % 3;
        cp_wait<2>();
        __syncthreads();
        uint32_t stg = sbase + (uint32_t)s * SSTR;

        uint32_t ah[2][MI][4], al[2][MI][4];
        uint32_t bh[2][NI][2], bl[2][NI][2];
#pragma unroll
        for (int u = 0; u < 2; u++) {
            uint32_t koff = (uint32_t)(u * 32);
#pragma unroll
            for (int mi = 0; mi < MI; mi++) {
                ldsm4(ah[u][mi], stg + OFF_AH + aRel + mi * (16 * 80) + koff);
                ldsm4(al[u][mi], stg + OFF_AL + aRel + mi * (16 * 80) + koff);
            }
#pragma unroll
            for (int n2 = 0; n2 < NI / 2; n2++) {
                uint32_t r4[4];
                ldsm4(r4, stg + OFF_BH + bRel + n2 * (16 * 80) + koff);
                bh[u][2*n2][0] = r4[0]; bh[u][2*n2][1] = r4[1];
                bh[u][2*n2+1][0] = r4[2]; bh[u][2*n2+1][1] = r4[3];
                ldsm4(r4, stg + OFF_BL + bRel + n2 * (16 * 80) + koff);
                bl[u][2*n2][0] = r4[0]; bl[u][2*n2][1] = r4[1];
                bl[u][2*n2+1][0] = r4[2]; bl[u][2*n2+1][1] = r4[3];
            }
        }
#pragma unroll
        for (int u = 0; u < 2; u++)
#pragma unroll
            for (int mi = 0; mi < MI; mi++)
#pragma unroll
                for (int ni = 0; ni < NI; ni++) {
                    mma16816(acc[mi][ni], ah[u][mi], bh[u][ni]);
                    mma16816(acc[mi][ni], al[u][mi], bh[u][ni]);
                    mma16816(acc[mi][ni], ah[u][mi], bl[u][ni]);
                }
        __syncthreads();
        if (kc + 3 < nk) load_stage(s, (kc + 3) * 32);
        cp_commit();
    }

#pragma unroll
    for (int mi = 0; mi < MI; mi++) {
        int row0 = m0 + wm * WM + mi * 16 + g;
#pragma unroll
        for (int ni = 0; ni < NI; ni++) {
            int col = n0 + wn * WN + ni * 8 + 2 * t;
            if (MODE == 0) {
                float2 v0, v1;
                v0.x = acc[mi][ni][0]; v0.y = acc[mi][ni][1];
                v1.x = acc[mi][ni][2]; v1.y = acc[mi][ni][3];
                *(float2*)(C + (size_t)row0 * N + col)       = v0;
                *(float2*)(C + (size_t)(row0 + 8) * N + col) = v1;
            } else {
#pragma unroll
                for (int hrow = 0; hrow < 2; hrow++) {
                    int row = row0 + hrow * 8;
                    float x0 = acc[mi][ni][hrow*2+0];
                    float x1 = acc[mi][ni][hrow*2+1];
                    if (RELU) { x0 = fmaxf(x0, 0.f); x1 = fmaxf(x1, 0.f); }
                    uint32_t lw;
                    uint32_t hw = pack_split2(x0, x1, lw);
                    size_t e = ((size_t)row * N + col) >> 1;
                    ((uint32_t*)Ch)[e] = hw;
                    ((uint32_t*)Cl)[e] = lw;
                }
            }
        }
    }
}

// ===========================================================================
// x = x_in + t_pos + s_pos  (+ bf16 split planes), float4 vectorized
// ===========================================================================
__global__ void add_pos_kernel(const float* __restrict__ x,
                               const float* __restrict__ tpos,
                               const float* __restrict__ spos) {
    int i4 = blockIdx.x * blockDim.x + threadIdx.x;
    if (i4 >= NM * NE / 4) return;
    int i = i4 * 4;
    int e = i % NE;
    int s = (i / NE) % NS;
    float4 xv = *(const float4*)(x + i);
    float4 tv = *(const float4*)(tpos + (s / NT) * NE + e);
    float4 sv = *(const float4*)(spos + (s % NT) * NE + e);
    float4 v;
    v.x = xv.x + tv.x + sv.x; v.y = xv.y + tv.y + sv.y;
    v.z = xv.z + tv.z + sv.z; v.w = xv.w + tv.w + sv.w;
    *(float4*)(g_x + i) = v;
    uint32_t lw0, lw1;
    uint32_t hw0 = pack_split2(v.x, v.y, lw0);
    uint32_t hw1 = pack_split2(v.z, v.w, lw1);
    uint2 hv, lv;
    hv.x = hw0; hv.y = hw1; lv.x = lw0; lv.y = lw1;
    *(uint2*)((uint32_t*)g_xh + i4 * 2) = hv;
    *(uint2*)((uint32_t*)g_xl + i4 * 2) = lv;
}

__global__ void pad_kernel() {
    int i = blockIdx.x * blockDim.x + threadIdx.x;
    if (i < NB * NS) g_pad[i] = (g_x[(size_t)i * NE] == 0.0f) ? 1 : 0;
}

// ===========================================================================
// scores_mma: 128x128 tile of q.k^T * scale, causal+pad masked -> fp32 attn.
// Triangular launch: blockIdx.x linearizes the 36 (qt,kt) pairs with kt<=qt.
// ===========================================================================
__global__ void __launch_bounds__(256)
scores_mma(const __nv_bfloat16* __restrict__ qkvh,
           const __nv_bfloat16* __restrict__ qkvl,
           float* __restrict__ attn) {
    int p = blockIdx.x;                       // 0..35
    int qt = 0;
    while ((qt + 1) * (qt + 2) / 2 <= p) qt++;
    int kt = p - qt * (qt + 1) / 2;
    int bh = blockIdx.y;
    int b = bh / NH, h = bh % NH;

    extern __shared__ char smem[];
    uint32_t sb = smem_u32(smem);
    const uint32_t QH = 0, QL = 128*144, KH = 2*128*144, KL = 3*128*144;

    int tid = threadIdx.x, lane = tid & 31, wid = tid >> 5;
    int wm = wid >> 1, wn = wid & 1;
    int g = lane >> 2, t = lane & 3;

    for (int idx = tid; idx < 128 * 8; idx += 256) {
        int r = idx >> 3, c = idx & 7;
        size_t qrow = (size_t)(b * NS + qt * 128 + r) * NQKV + h * DK + c * 8;
        size_t krow = (size_t)(b * NS + kt * 128 + r) * NQKV + NE + h * DK + c * 8;
        uint32_t d = (uint32_t)(r * 144 + c * 16);
        cp16(sb + QH + d, qkvh + qrow);
        cp16(sb + QL + d, qkvl + qrow);
        cp16(sb + KH + d, qkvh + krow);
        cp16(sb + KL + d, qkvl + krow);
    }
    cp_commit();
    cp_wait<0>();
    __syncthreads();

    uint32_t aRel = (uint32_t)((wm * 32 + (lane & 15)) * 144 + ((lane >> 4) & 1) * 16);
    uint32_t bRel = (uint32_t)((wn * 64 + (lane & 7) + ((lane >> 4) << 3)) * 144
                               + ((lane >> 3) & 1) * 16);

    float acc[2][8][4];
#pragma unroll
    for (int mi = 0; mi < 2; mi++)
#pragma unroll
        for (int ni = 0; ni < 8; ni++)
#pragma unroll
            for (int j = 0; j < 4; j++) acc[mi][ni][j] = 0.f;

#pragma unroll
    for (int kk = 0; kk < 4; kk++) {
        uint32_t koff = (uint32_t)(kk * 32);
        uint32_t ah[2][4], al[2][4];
#pragma unroll
        for (int mi = 0; mi < 2; mi++) {
            ldsm4(ah[mi], sb + QH + aRel + mi * (16 * 144) + koff);
            ldsm4(al[mi], sb + QL + aRel + mi * (16 * 144) + koff);
        }
        uint32_t bh_[8][2], bl_[8][2];
#pragma unroll
        for (int n2 = 0; n2 < 4; n2++) {
            uint32_t r4[4];
            ldsm4(r4, sb + KH + bRel + n2 * (16 * 144) + koff);
            bh_[2*n2][0] = r4[0]; bh_[2*n2][1] = r4[1];
            bh_[2*n2+1][0] = r4[2]; bh_[2*n2+1][1] = r4[3];
            ldsm4(r4, sb + KL + bRel + n2 * (16 * 144) + koff);
            bl_[2*n2][0] = r4[0]; bl_[2*n2][1] = r4[1];
            bl_[2*n2+1][0] = r4[2]; bl_[2*n2+1][1] = r4[3];
        }
#pragma unroll
        for (int mi = 0; mi < 2; mi++)
#pragma unroll
            for (int ni = 0; ni < 8; ni++) {
                mma16816(acc[mi][ni], ah[mi], bh_[ni]);
                mma16816(acc[mi][ni], al[mi], bh_[ni]);
                mma16816(acc[mi][ni], ah[mi], bl_[ni]);
            }
    }

    float* out = attn + (size_t)bh * NS * NS;
    const float scale = 0.125f;
#pragma unroll
    for (int mi = 0; mi < 2; mi++) {
#pragma unroll
        for (int hrow = 0; hrow < 2; hrow++) {
            int qi = qt * 128 + wm * 32 + mi * 16 + g + hrow * 8;
#pragma unroll
            for (int ni = 0; ni < 8; ni++) {
                int ki = kt * 128 + wn * 64 + ni * 8 + 2 * t;
                float v0 = acc[mi][ni][hrow*2+0] * scale;
                float v1 = acc[mi][ni][hrow*2+1] * scale;
                if (ki     > qi || g_pad[b * NS + ki])     v0 = -1e9f;
                if (ki + 1 > qi || g_pad[b * NS + ki + 1]) v1 = -1e9f;
                float2 v; v.x = v0; v.y = v1;
                *(float2*)(out + (size_t)qi * NS + ki) = v;
            }
        }
    }
}

// ===========================================================================
// Warp-per-row softmax (round-8 form): writes fp32 probs (incl causal zeros)
// and bf16 split planes (zero-padded to the 128-tile boundary).
// ===========================================================================
__global__ void __launch_bounds__(256)
softmax_kernel(float* __restrict__ attn,
               __nv_bfloat16* __restrict__ ph,
               __nv_bfloat16* __restrict__ pl) {
    int wid = threadIdx.x >> 5, lane = threadIdx.x & 31;
    int q  = blockIdx.x * 8 + wid;
    int bh = blockIdx.y;
    size_t pbase = (size_t)bh * NS * NS + (size_t)q * NS;
    float* row = attn + pbase;
    int n = q + 1;
    int npad = (n + 127) & ~127;

    float4 v[8];
    float m = -1e30f;
#pragma unroll
    for (int j = 0; j < 8; j++) {
        int e0 = (lane + 32 * j) * 4;
        if (e0 < n) {
            float4 tv = *(const float4*)(row + e0);
            v[j].x = tv.x;
            v[j].y = (e0 + 1 < n) ? tv.y : -1e30f;
            v[j].z = (e0 + 2 < n) ? tv.z : -1e30f;
            v[j].w = (e0 + 3 < n) ? tv.w : -1e30f;
        } else {
            v[j].x = -1e30f; v[j].y = -1e30f; v[j].z = -1e30f; v[j].w = -1e30f;
        }
        m = fmaxf(m, fmaxf(fmaxf(v[j].x, v[j].y), fmaxf(v[j].z, v[j].w)));
    }
#pragma unroll
    for (int o = 16; o; o >>= 1) m = fmaxf(m, __shfl_xor_sync(0xffffffffu, m, o));

    float s = 0.f;
#pragma unroll
    for (int j = 0; j < 8; j++) {
        v[j].x = __expf(v[j].x - m);
        v[j].y = __expf(v[j].y - m);
        v[j].z = __expf(v[j].z - m);
        v[j].w = __expf(v[j].w - m);
        s += (v[j].x + v[j].y) + (v[j].z + v[j].w);
    }
#pragma unroll
    for (int o = 16; o; o >>= 1) s += __shfl_xor_sync(0xffffffffu, s, o);
    float inv = 1.0f / s;

#pragma unroll
    for (int j = 0; j < 8; j++) {
        int e0 = (lane + 32 * j) * 4;
        float4 p;
        p.x = v[j].x * inv; p.y = v[j].y * inv;
        p.z = v[j].z * inv; p.w = v[j].w * inv;
        *(float4*)(row + e0) = p;             // probs for i<n, exact 0 beyond
        if (e0 < npad) {
            uint32_t lw0, lw1;
            uint32_t hw0 = pack_split2(p.x, p.y, lw0);
            uint32_t hw1 = pack_split2(p.z, p.w, lw1);
            uint2 hv, lv;
            hv.x = hw0; hv.y = hw1; lv.x = lw0; lv.y = lw1;
            *(uint2*)((uint32_t*)ph + ((pbase + e0) >> 1)) = hv;
            *(uint2*)((uint32_t*)pl + ((pbase + e0) >> 1)) = lv;
        }
    }
}

// ===========================================================================
// ctx_mma: ctx[128q x 64d] = attn_planes @ v_planes (causal kt loop).
// Double-buffered across kt tiles.
// ===========================================================================
#define CTX_SSTR (2*128*272 + 2*128*144)   // 106,496 bytes per stage

__global__ void __launch_bounds__(256)
ctx_mma(const __nv_bfloat16* __restrict__ ph, const __nv_bfloat16* __restrict__ pl,
        const __nv_bfloat16* __restrict__ qkvh, const __nv_bfloat16* __restrict__ qkvl,
        __nv_bfloat16* __restrict__ ch, __nv_bfloat16* __restrict__ cl) {
    int qt = (int)gridDim.x - 1 - (int)blockIdx.x;   // heavy tiles first
    int bh = blockIdx.y;
    int b = bh / NH, h = bh % NH;

    extern __shared__ char smem[];
    uint32_t sb = smem_u32(smem);
    const uint32_t AH = 0, AL = 128*272, VH = 2*128*272, VL = 2*128*272 + 128*144;

    int tid = threadIdx.x, lane = tid & 31, wid = tid >> 5;
    int wm = wid >> 1, wn = wid & 1;
    int g = lane >> 2, t = lane & 3;

    uint32_t aRel = (uint32_t)((wm * 32 + (lane & 15)) * 272 + ((lane >> 4) & 1) * 16);

    auto load_tile = [&](int kt, int st) {
        uint32_t base = sb + (uint32_t)st * CTX_SSTR;
        for (int idx = tid; idx < 128 * 16; idx += 256) {
            int r = idx >> 4, c = idx & 15;
            size_t arow = (size_t)bh * NS * NS + (size_t)(qt * 128 + r) * NS
                        + kt * 128 + c * 8;
            uint32_t d = (uint32_t)(r * 272 + c * 16);
            cp16(base + AH + d, ph + arow);
            cp16(base + AL + d, pl + arow);
        }
        for (int idx = tid; idx < 128 * 8; idx += 256) {
            int r = idx >> 3, c = idx & 7;
            size_t vrow = (size_t)(b * NS + kt * 128 + r) * NQKV + 1536 + h * DK + c * 8;
            uint32_t d = (uint32_t)(r * 144 + c * 16);
            cp16(base + VH + d, qkvh + vrow);
            cp16(base + VL + d, qkvl + vrow);
        }
    };

    float acc[2][4][4];
#pragma unroll
    for (int mi = 0; mi < 2; mi++)
#pragma unroll
        for (int ni = 0; ni < 4; ni++)
#pragma unroll
            for (int j = 0; j < 4; j++) acc[mi][ni][j] = 0.f;

    load_tile(0, 0);
    cp_commit();

    for (int kt = 0; kt <= qt; kt++) {
        int s = kt & 1;
        if (kt < qt) load_tile(kt + 1, s ^ 1);
        cp_commit();
        cp_wait<1>();
        __syncthreads();
        uint32_t base = sb + (uint32_t)s * CTX_SSTR;

#pragma unroll
        for (int kk = 0; kk < 8; kk++) {
            uint32_t koff = (uint32_t)(kk * 32);
            uint32_t ah[2][4], al[2][4];
#pragma unroll
            for (int mi = 0; mi < 2; mi++) {
                ldsm4(ah[mi], base + AH + aRel + mi * (16 * 272) + koff);
                ldsm4(al[mi], base + AL + aRel + mi * (16 * 272) + koff);
            }
            uint32_t vrowRel = (uint32_t)((kk * 16 + (lane & 15)) * 144);
            uint32_t bh_[4][2], bl_[4][2];
#pragma unroll
            for (int ni = 0; ni < 4; ni++) {
                uint32_t coff = (uint32_t)((wn * 32 + ni * 8) * 2);
                ldsm2t(bh_[ni], base + VH + vrowRel + coff);
                ldsm2t(bl_[ni], base + VL + vrowRel + coff);
            }
#pragma unroll
            for (int mi = 0; mi < 2; mi++)
#pragma unroll
                for (int ni = 0; ni < 4; ni++) {
                    mma16816(acc[mi][ni], ah[mi], bh_[ni]);
                    mma16816(acc[mi][ni], al[mi], bh_[ni]);
                    mma16816(acc[mi][ni], ah[mi], bl_[ni]);
                }
        }
        __syncthreads();
    }

#pragma unroll
    for (int mi = 0; mi < 2; mi++) {
#pragma unroll
        for (int ni = 0; ni < 4; ni++) {
            int dcol = h * DK + wn * 32 + ni * 8 + 2 * t;
#pragma unroll
            for (int hrow = 0; hrow < 2; hrow++) {
                int q = qt * 128 + wm * 32 + mi * 16 + g + hrow * 8;
                uint32_t lw;
                uint32_t hw = pack_split2(acc[mi][ni][hrow*2], acc[mi][ni][hrow*2+1], lw);
                size_t e = ((size_t)(b * NS + q) * NE + dcol) >> 1;
                ((uint32_t*)ch)[e] = hw;
                ((uint32_t*)cl)[e] = lw;
            }
        }
    }
}

// ===========================================================================
// x = LayerNorm(y1 [+ y2] + x) * g + b  (round-8 form: 256 thr, smem buf;
// optional extra fp32 destination xout)
// ===========================================================================
__global__ void ln_kernel(const float* __restrict__ y1,
                          const float* __restrict__ y2,
                          float* __restrict__ xio,
                          float* __restrict__ xout,
                          const float* __restrict__ gamma,
                          const float* __restrict__ beta) {
    int row = blockIdx.x;
    __shared__ float buf[NE];
    __shared__ float red[8];
    int tid = threadIdx.x;
    size_t rbase = (size_t)row * NE;

    float s = 0.f;
    if (tid < 192) {
        int i = tid * 4;
        float4 a = *(const float4*)(y1 + rbase + i);
        float4 c = *(const float4*)(xio + rbase + i);
        float4 v;
        v.x = a.x + c.x; v.y = a.y + c.y; v.z = a.z + c.z; v.w = a.w + c.w;
        if (y2) {
            float4 d = *(const float4*)(y2 + rbase + i);
            v.x += d.x; v.y += d.y; v.z += d.z; v.w += d.w;
        }
        *(float4*)(buf + i) = v;
        s = (v.x + v.y) + (v.z + v.w);
    }
#pragma unroll
    for (int o = 16; o; o >>= 1) s += __shfl_xor_sync(0xffffffffu, s, o);
    if ((tid & 31) == 0) red[tid >> 5] = s;
    __syncthreads();
    if (tid < 32) {
        float r = (tid < 8) ? red[tid] : 0.f;
#pragma unroll
        for (int o = 4; o; o >>= 1) r += __shfl_xor_sync(0xffffffffu, r, o);
        if (tid == 0) red[0] = r;
    }
    __syncthreads();
    float mean = red[0] * (1.0f / NE);
    __syncthreads();

    float vs = 0.f;
    if (tid < 192) {
        float4 v = *(const float4*)(buf + tid * 4);
        float dx = v.x - mean, dy = v.y - mean, dz = v.z - mean, dw = v.w - mean;
        vs = (dx * dx + dy * dy) + (dz * dz + dw * dw);
    }
#pragma unroll
    for (int o = 16; o; o >>= 1) vs += __shfl_xor_sync(0xffffffffu, vs, o);
    if ((tid & 31) == 0) red[tid >> 5] = vs;
    __syncthreads();
    if (tid < 32) {
        float r = (tid < 8) ? red[tid] : 0.f;
#pragma unroll
        for (int o = 4; o; o >>= 1) r += __shfl_xor_sync(0xffffffffu, r, o);
        if (tid == 0) red[0] = r;
    }
    __syncthreads();
    float rstd = rsqrtf(red[0] * (1.0f / NE) + EPS);

    if (tid < 192) {
        int i = tid * 4;
        float4 v = *(const float4*)(buf + i);
        float4 gm = *(const float4*)(gamma + i);
        float4 bt = *(const float4*)(beta + i);
        float4 o;
        o.x = (v.x - mean) * rstd * gm.x + bt.x;
        o.y = (v.y - mean) * rstd * gm.y + bt.y;
        o.z = (v.z - mean) * rstd * gm.z + bt.z;
        o.w = (v.w - mean) * rstd * gm.w + bt.w;
        *(float4*)(xio + rbase + i) = o;
        if (xout) *(float4*)(xout + rbase + i) = o;
        uint32_t lw0, lw1;
        uint32_t hw0 = pack_split2(o.x, o.y, lw0);
        uint32_t hw1 = pack_split2(o.z, o.w, lw1);
        uint2 hv, lv;
        hv.x = hw0; hv.y = hw1; lv.x = lw0; lv.y = lw1;
        *(uint2*)((uint32_t*)g_xh + ((rbase + i) >> 1)) = hv;
        *(uint2*)((uint32_t*)g_xl + ((rbase + i) >> 1)) = lv;
    }
}

// ===========================================================================
extern "C" void kernel_launch(void* const* d_in, const int* in_sizes, int n_in,
                              void* d_out, int out_size) {
    const float* x    = (const float*)d_in[0];
    const float* tpos = (const float*)d_in[1];
    const float* spos = (const float*)d_in[2];
    const float* Wq   = (const float*)d_in[3];
    const float* Wk   = (const float*)d_in[4];
    const float* Wv   = (const float*)d_in[5];
    const float* Wo   = (const float*)d_in[6];
    const float* ln1g = (const float*)d_in[7];
    const float* ln1b = (const float*)d_in[8];
    const float* W1   = (const float*)d_in[9];
    const float* W2   = (const float*)d_in[10];
    const float* ln2g = (const float*)d_in[11];
    const float* ln2b = (const float*)d_in[12];

    float* out      = (float*)d_out;
    float* attn_out = out + (size_t)NM * NE;

    float *px, *ptmp, *ptmp2;
    __nv_bfloat16 *pxh, *pxl, *pqkvh, *pqkvl, *pch, *pcl, *phh, *phl, *pah, *pal;
    __nv_bfloat16 *pwqkvh, *pwqkvl, *pwoh, *pwol, *pw1h, *pw1l, *pw2h, *pw2l;
    cudaGetSymbolAddress((void**)&px,    g_x);
    cudaGetSymbolAddress((void**)&ptmp,  g_tmp);
    cudaGetSymbolAddress((void**)&ptmp2, g_tmp2);
    cudaGetSymbolAddress((void**)&pxh,   g_xh);
    cudaGetSymbolAddress((void**)&pxl,   g_xl);
    cudaGetSymbolAddress((void**)&pqkvh, g_qkvh);
    cudaGetSymbolAddress((void**)&pqkvl, g_qkvl);
    cudaGetSymbolAddress((void**)&pch,   g_ch);
    cudaGetSymbolAddress((void**)&pcl,   g_cl);
    cudaGetSymbolAddress((void**)&phh,   g_hh);
    cudaGetSymbolAddress((void**)&phl,   g_hl);
    cudaGetSymbolAddress((void**)&pah,   g_ah);
    cudaGetSymbolAddress((void**)&pal,   g_al);
    cudaGetSymbolAddress((void**)&pwqkvh, g_wqkvh);
    cudaGetSymbolAddress((void**)&pwqkvl, g_wqkvl);
    cudaGetSymbolAddress((void**)&pwoh,  g_woh);
    cudaGetSymbolAddress((void**)&pwol,  g_wol);
    cudaGetSymbolAddress((void**)&pw1h,  g_w1h);
    cudaGetSymbolAddress((void**)&pw1l,  g_w1l);
    cudaGetSymbolAddress((void**)&pw2h,  g_w2h);
    cudaGetSymbolAddress((void**)&pw2l,  g_w2l);

    const int SM_P  = 2 * (128 + 64) * 80 * 3;       //  92,160
    const int SM_SC = 4 * 128 * 144;                 //  73,728
    const int SM_CX = 2 * CTX_SSTR;                  // 212,992

    cudaFuncSetAttribute((const void*)bf16_gemm<0,false>,
        cudaFuncAttributeMaxDynamicSharedMemorySize, SM_P);
    cudaFuncSetAttribute((const void*)bf16_gemm<1,false>,
        cudaFuncAttributeMaxDynamicSharedMemorySize, SM_P);
    cudaFuncSetAttribute((const void*)bf16_gemm<1,true>,
        cudaFuncAttributeMaxDynamicSharedMemorySize, SM_P);
    cudaFuncSetAttribute((const void*)scores_mma,
        cudaFuncAttributeMaxDynamicSharedMemorySize, SM_SC);
    cudaFuncSetAttribute((const void*)ctx_mma,
        cudaFuncAttributeMaxDynamicSharedMemorySize, SM_CX);

    add_pos_kernel<<<(NM * NE / 4 + 255) / 256, 256>>>(x, tpos, spos);
    pad_kernel<<<(NB * NS + 255) / 256, 256>>>();

    {
        dim3 blk(32, 8);
        transpose_split_ee<<<dim3(NE/32, NE/32, NL*4), blk>>>(
            Wq, Wk, Wv, Wo, pwqkvh, pwqkvl, pwoh, pwol);
        transpose_split_w<<<dim3(DFF/32, NE/32, NL), blk>>>(W1, pw1h, pw1l, NE, DFF);
        transpose_split_w<<<dim3(NE/32, DFF/32, NL), blk>>>(W2, pw2h, pw2l, DFF, NE);
    }

    dim3 gQKV(NQKV / 64, NM / 128, 1);         // (36, 16)
    dim3 gWo(NE / 64, NM / 128, 2);            // (12, 16, 2) split-K merged
    dim3 gFF1(DFF / 64, NM / 128, 1);          // (48, 16)
    dim3 gFF2(NE / 64, NM / 128, 2);           // (12, 16, 2) split-K merged
    dim3 gScores(36, NB * NH);                 // triangular (qt,kt) pairs
    dim3 gSoft(NS / 8, NB * NH);               // (128, 24) warp-per-row
    dim3 gCtx(NS / 128, NB * NH);              // (8, 24)

    for (int l = 0; l < NL; l++) {
        size_t oE = (size_t)l * NE * NE, oF = (size_t)l * NE * DFF;
        size_t oQ = (size_t)l * NQKV * NE;
        float* attn_l = attn_out + (size_t)l * NB * NH * NS * NS;
        float* xout2 = (l == NL - 1) ? out : nullptr;

        bf16_gemm<1,false><<<gQKV, 128, SM_P>>>(
            pxh, pxl, pwqkvh + oQ, pwqkvl + oQ,
            nullptr, nullptr, pqkvh, pqkvl, NM, NQKV, NE, NE, 0);

        scores_mma<<<gScores, 256, SM_SC>>>(pqkvh, pqkvl, attn_l);
        softmax_kernel<<<gSoft, 256>>>(attn_l, pah, pal);
        ctx_mma<<<gCtx, 256, SM_CX>>>(pah, pal, pqkvh, pqkvl, pch, pcl);

        bf16_gemm<0,false><<<gWo, 128, SM_P>>>(
            pch, pcl, pwoh + oE, pwol + oE, ptmp, ptmp2, nullptr, nullptr,
            NM, NE, NE, 384, 384);
        ln_kernel<<<NM, 256>>>(ptmp, ptmp2, px, nullptr,
                               ln1g + (size_t)l * NE, ln1b + (size_t)l * NE);

        bf16_gemm<1,true><<<gFF1, 128, SM_P>>>(
            pxh, pxl, pw1h + oF, pw1l + oF, nullptr, nullptr, phh, phl,
            NM, DFF, NE, NE, 0);

        bf16_gemm<0,false><<<gFF2, 128, SM_P>>>(
            phh, phl, pw2h + oF, pw2l + oF, ptmp, ptmp2, nullptr, nullptr,
            NM, NE, DFF, 1536, 1536);
        ln_kernel<<<NM, 256>>>(ptmp, ptmp2, px, xout2,
                               ln2g + (size_t)l * NE, ln2b + (size_t)l * NE);
    }
}